// round 10
// baseline (speedup 1.0000x reference)
#include <cuda_runtime.h>
#include <cuda_bf16.h>
#include <cstdint>
#include <math.h>

#define Bsz 4
#define Nn 4096
#define DIMc 256
#define Hh 8
#define DHd 64
#define Pp 2
#define INNERc 512
#define MQ (Bsz*Nn)      /* 16384 */
#define MKV (2*Bsz*Nn)   /* 32768 */

typedef __nv_bfloat16 bf16;

// ---------------- scratch (device globals) ----------------
__device__ bf16  g_qlnh[MQ * INNERc];
__device__ bf16  g_qlnl[MQ * INNERc];
__device__ float g_q   [MQ * INNERc];
__device__ bf16  g_nh  [MKV * DIMc];
__device__ bf16  g_nl  [MKV * DIMc];
__device__ float g_kv  [MKV * 2 * INNERc];
__device__ bf16  g_aoh [MQ * INNERc];
__device__ bf16  g_aol [MQ * INNERc];
__device__ bf16  g_wqTh[INNERc * INNERc];
__device__ bf16  g_wqTl[INNERc * INNERc];
__device__ bf16  g_wkvTh[2 * INNERc * DIMc];
__device__ bf16  g_wkvTl[2 * INNERc * DIMc];
__device__ bf16  g_wouth[DIMc * INNERc];
__device__ bf16  g_woutl[DIMc * INNERc];
__device__ float g_biasq [INNERc];
__device__ float g_biaskv[2 * INNERc];

// ================= helpers =================
__device__ __forceinline__ uint32_t smem_u32(const void* p){
    uint32_t a;
    asm("{ .reg .u64 t; cvta.to.shared.u64 t, %1; cvt.u32.u64 %0, t; }" : "=r"(a) : "l"(p));
    return a;
}
__device__ __forceinline__ void bsplit(float v, bf16& h, bf16& l){
    h = __float2bfloat16(v);
    l = __float2bfloat16(v - __bfloat162float(h));
}
__device__ __forceinline__ void mma_bf16(float d[4], const uint32_t a[4], const uint32_t b[2]){
    asm volatile("mma.sync.aligned.m16n8k16.row.col.f32.bf16.bf16.f32 "
        "{%0,%1,%2,%3}, {%4,%5,%6,%7}, {%8,%9}, {%0,%1,%2,%3};"
        : "+f"(d[0]),"+f"(d[1]),"+f"(d[2]),"+f"(d[3])
        : "r"(a[0]),"r"(a[1]),"r"(a[2]),"r"(a[3]),"r"(b[0]),"r"(b[1]));
}
__device__ __forceinline__ void ldsm4(uint32_t r[4], uint32_t addr){
    asm volatile("ldmatrix.sync.aligned.m8n8.x4.shared.b16 {%0,%1,%2,%3}, [%4];"
        : "=r"(r[0]),"=r"(r[1]),"=r"(r[2]),"=r"(r[3]) : "r"(addr));
}
__device__ __forceinline__ void cp16(uint32_t dst, const void* src){
    asm volatile("cp.async.cg.shared.global [%0], [%1], 16;" :: "r"(dst), "l"(src));
}
// swizzled byte offset within a plane: row (0..127) has 64B = 4 x 16B slots
__device__ __forceinline__ uint32_t swz(int r, int s){
    return (uint32_t)(r * 64 + ((s ^ ((r >> 1) & 3)) << 4));
}

// ================= bf16x3 tensor-core GEMM (unchanged from R9) =================
#define TILE_B 8192
#define STAGE_B 32768
#define GEMM_SMEM (3*STAGE_B)

template<int HAS_BIAS>
__global__ void __launch_bounds__(256, 2)
bf16x3_gemm(const bf16* __restrict__ Ah, const bf16* __restrict__ Al,
            const bf16* __restrict__ Bh, const bf16* __restrict__ Bl,
            const float* __restrict__ bias, float* __restrict__ C,
            int Ntot, int K)
{
    extern __shared__ char smem[];
    const uint32_t sb = smem_u32(smem);
    const int tid = threadIdx.x, lane = tid & 31, wid = tid >> 5;
    const int wm = wid >> 2, wn = wid & 3;
    const int bm = blockIdx.y * 128, bn = blockIdx.x * 128;
    const int NC = K >> 5;

    const int lr  = tid >> 2;
    const int lcc = tid & 3;
    const uint32_t w0 = swz(lr, lcc), w1 = swz(lr + 64, lcc);

    uint32_t aoff[2][4], boff[2][2];
    #pragma unroll
    for (int ks = 0; ks < 2; ks++){
        const int slot = (lane >> 4) + ks * 2;
        #pragma unroll
        for (int i = 0; i < 4; i++)
            aoff[ks][i] = swz(wm*64 + i*16 + (lane & 15), slot);
        #pragma unroll
        for (int jp = 0; jp < 2; jp++)
            boff[ks][jp] = 2*TILE_B + swz(wn*32 + jp*16 + (lane & 15), slot);
    }

    auto load_stage = [&](int buf, int kc){
        uint32_t base = sb + buf * STAGE_B;
        size_t ao = (size_t)(bm + lr) * K + kc + lcc * 8;
        size_t bo = (size_t)(bn + lr) * K + kc + lcc * 8;
        size_t row64 = (size_t)64 * K;
        cp16(base + w0,            Ah + ao);
        cp16(base + w1,            Ah + ao + row64);
        cp16(base + TILE_B + w0,   Al + ao);
        cp16(base + TILE_B + w1,   Al + ao + row64);
        cp16(base + 2*TILE_B + w0, Bh + bo);
        cp16(base + 2*TILE_B + w1, Bh + bo + row64);
        cp16(base + 3*TILE_B + w0, Bl + bo);
        cp16(base + 3*TILE_B + w1, Bl + bo + row64);
        asm volatile("cp.async.commit_group;" ::: "memory");
    };

    float acc[4][4][4] = {};

    auto compute = [&](int buf){
        uint32_t base = sb + buf * STAGE_B;
        #pragma unroll
        for (int ks = 0; ks < 2; ks++){
            uint32_t BH[4][2], BL[4][2];
            #pragma unroll
            for (int jp = 0; jp < 2; jp++){
                uint32_t a = base + boff[ks][jp];
                uint32_t r4[4];
                ldsm4(r4, a);
                BH[jp*2][0]=r4[0]; BH[jp*2+1][0]=r4[1]; BH[jp*2][1]=r4[2]; BH[jp*2+1][1]=r4[3];
                ldsm4(r4, a + TILE_B);
                BL[jp*2][0]=r4[0]; BL[jp*2+1][0]=r4[1]; BL[jp*2][1]=r4[2]; BL[jp*2+1][1]=r4[3];
            }
            #pragma unroll
            for (int i = 0; i < 4; i++){
                uint32_t a = base + aoff[ks][i];
                uint32_t ah[4], al_[4];
                ldsm4(ah,  a);
                ldsm4(al_, a + TILE_B);
                #pragma unroll
                for (int j = 0; j < 4; j++) mma_bf16(acc[i][j], ah,  BH[j]);
                #pragma unroll
                for (int j = 0; j < 4; j++) mma_bf16(acc[i][j], ah,  BL[j]);
                #pragma unroll
                for (int j = 0; j < 4; j++) mma_bf16(acc[i][j], al_, BH[j]);
            }
        }
    };

    load_stage(0, 0);
    load_stage(1, 32);

    for (int c = 0; c < NC; c++){
        if (c < NC - 1) asm volatile("cp.async.wait_group 1;" ::: "memory");
        else            asm volatile("cp.async.wait_group 0;" ::: "memory");
        __syncthreads();
        if (c + 2 < NC) load_stage((c + 2) % 3, (c + 2) * 32);
        compute(c % 3);
    }

    #pragma unroll
    for (int i = 0; i < 4; i++){
        int r0 = bm + wm*64 + i*16 + (lane >> 2);
        #pragma unroll
        for (int j = 0; j < 4; j++){
            int c0 = bn + wn*32 + j*8 + (lane & 3)*2;
            float b0 = 0.f, b1 = 0.f;
            if (HAS_BIAS){ b0 = bias[c0]; b1 = bias[c0+1]; }
            *(float2*)(C + (size_t)r0 * Ntot + c0)     = make_float2(acc[i][j][0]+b0, acc[i][j][1]+b1);
            *(float2*)(C + (size_t)(r0+8) * Ntot + c0) = make_float2(acc[i][j][2]+b0, acc[i][j][3]+b1);
        }
    }
}

// ================= merged weight prep (single launch) =================
__device__ __forceinline__ void tss_body(const float* in, const float* g,
                                         bf16* oh, bf16* ol, int R, int C,
                                         int bx, int by, int tx, int ty){
    __shared__ float tile[32][33];
    int c0 = bx * 32, r0 = by * 32;
    #pragma unroll
    for (int i = 0; i < 32; i += 8){
        int r = r0 + ty + i;
        tile[ty + i][tx] = in[(size_t)r * C + c0 + tx] * g[r];
    }
    __syncthreads();
    #pragma unroll
    for (int i = 0; i < 32; i += 8){
        float v = tile[tx][ty + i];
        bf16 h, l; bsplit(v, h, l);
        size_t o = (size_t)(c0 + ty + i) * R + r0 + tx;
        oh[o] = h; ol[o] = l;
    }
}
__device__ __forceinline__ void fold_body(const float* W, const float* beta,
                                          const float* base, float* out,
                                          int K, int N, int n, int lane){
    float s = 0.f;
    for (int k = lane; k < K; k += 32) s += beta[k] * W[(size_t)k * N + n];
    #pragma unroll
    for (int o = 16; o > 0; o >>= 1) s += __shfl_xor_sync(0xffffffffu, s, o);
    if (lane == 0) out[n] = s + (base ? base[n] : 0.f);
}

__global__ void prep_kernel(const float* __restrict__ Wq, const float* __restrict__ lnqg, const float* __restrict__ lnqb,
                            const float* __restrict__ Wk, const float* __restrict__ lnkg, const float* __restrict__ lnkb, const float* __restrict__ bk,
                            const float* __restrict__ Wv, const float* __restrict__ lnvg, const float* __restrict__ lnvb, const float* __restrict__ bv,
                            const float* __restrict__ Wout,
                            bf16* __restrict__ wqTh, bf16* __restrict__ wqTl,
                            bf16* __restrict__ wkvTh, bf16* __restrict__ wkvTl,
                            bf16* __restrict__ wouth, bf16* __restrict__ woutl,
                            float* __restrict__ biasq, float* __restrict__ biaskv){
    int id = blockIdx.x;
    int tx = threadIdx.x, ty = threadIdx.y;           // (32, 8)
    if (id < 256){
        tss_body(Wq, lnqg, wqTh, wqTl, INNERc, INNERc, id & 15, id >> 4, tx, ty);
    } else if (id < 384){
        int l = id - 256;
        tss_body(Wk, lnkg, wkvTh, wkvTl, DIMc, INNERc, l & 15, l >> 4, tx, ty);
    } else if (id < 512){
        int l = id - 384;
        tss_body(Wv, lnvg, wkvTh + (size_t)INNERc*DIMc, wkvTl + (size_t)INNERc*DIMc,
                 DIMc, INNERc, l & 15, l >> 4, tx, ty);
    } else if (id < 1024){
        int i = (id - 512) * 256 + ty * 32 + tx;
        bf16 h, l; bsplit(Wout[i], h, l);
        wouth[i] = h; woutl[i] = l;
    } else if (id < 1088){
        int n = (id - 1024) * 8 + ty;
        fold_body(Wq, lnqb, nullptr, biasq, INNERc, INNERc, n, tx);
    } else if (id < 1152){
        int n = (id - 1088) * 8 + ty;
        fold_body(Wk, lnkb, bk, biaskv, DIMc, INNERc, n, tx);
    } else {
        int n = (id - 1152) * 8 + ty;
        fold_body(Wv, lnvb, bv, biaskv + INNERc, DIMc, INNERc, n, tx);
    }
}

// ================= block reduce =================
__device__ __forceinline__ float2 blockReduce2(float a, float b) {
    __shared__ float2 sbuf[8];
    #pragma unroll
    for (int o = 16; o > 0; o >>= 1) {
        a += __shfl_xor_sync(0xffffffffu, a, o);
        b += __shfl_xor_sync(0xffffffffu, b, o);
    }
    int w = threadIdx.x >> 5;
    if ((threadIdx.x & 31) == 0) sbuf[w] = make_float2(a, b);
    __syncthreads();
    if (w == 0) {
        int nw = blockDim.x >> 5;
        float2 r = (threadIdx.x < nw) ? sbuf[threadIdx.x] : make_float2(0.f, 0.f);
        #pragma unroll
        for (int o = 4; o > 0; o >>= 1) {
            r.x += __shfl_xor_sync(0xffffffffu, r.x, o);
            r.y += __shfl_xor_sync(0xffffffffu, r.y, o);
        }
        if (threadIdx.x == 0) sbuf[0] = r;
    }
    __syncthreads();
    return sbuf[0];
}

// ============ LN over concat (512) ============
__global__ void lnq_kernel(const float* __restrict__ x, const float* __restrict__ px,
                           bf16* __restrict__ oh, bf16* __restrict__ ol) {
    int row = blockIdx.x;
    int t = threadIdx.x;
    float v0 = x [row * DIMc + t];
    float v1 = px[row * DIMc + t];
    float2 r = blockReduce2(v0 + v1, v0 * v0 + v1 * v1);
    float mean = r.x * (1.0f / 512.0f);
    float var  = r.y * (1.0f / 512.0f) - mean * mean;
    float rstd = rsqrtf(var + 1e-5f);
    bf16 h, l;
    bsplit((v0 - mean) * rstd, h, l); oh[row * INNERc + t] = h;       ol[row * INNERc + t] = l;
    bsplit((v1 - mean) * rstd, h, l); oh[row * INNERc + 256 + t] = h; ol[row * INNERc + 256 + t] = l;
}

// ============ LN over kv (256) ============
__global__ void lnkv_kernel(const float* __restrict__ x, const float* __restrict__ px,
                            bf16* __restrict__ nh, bf16* __restrict__ nl) {
    int row = blockIdx.x;
    int t = threadIdx.x;
    const float* src = (row < Bsz * Nn) ? x : px;
    int r2 = (row < Bsz * Nn) ? row : row - Bsz * Nn;
    float v = src[r2 * DIMc + t];
    float2 r = blockReduce2(v, v * v);
    float mean = r.x * (1.0f / 256.0f);
    float var  = r.y * (1.0f / 256.0f) - mean * mean;
    float rstd = rsqrtf(var + 1e-5f);
    bf16 h, l;
    bsplit((v - mean) * rstd, h, l);
    nh[row * DIMc + t] = h; nl[row * DIMc + t] = l;
}

// ============ offsets projection (fp32) — writes transposed (B,H,P,N) ============
__global__ void off_kernel(const float* __restrict__ q, const float* __restrict__ Woff,
                           const float* __restrict__ boff, float* __restrict__ off_out) {
    __shared__ float w[16][INNERc];
    int tid = threadIdx.x;
    for (int i = tid; i < 16 * INNERc; i += 128) w[i >> 9][i & 511] = Woff[i];
    __syncthreads();
    int m = blockIdx.x * 128 + tid;        // b*N + n
    const float* qr = q + (size_t)m * INNERc;
    float acc[16];
    #pragma unroll
    for (int j = 0; j < 16; j++) acc[j] = boff[j];
    for (int k0 = 0; k0 < INNERc; k0 += 4){
        float4 qv = *(const float4*)(qr + k0);
        #pragma unroll
        for (int j = 0; j < 16; j++)
            acc[j] += qv.x * w[j][k0] + qv.y * w[j][k0+1] + qv.z * w[j][k0+2] + qv.w * w[j][k0+3];
    }
    int b = m >> 12, n = m & 4095;
    #pragma unroll
    for (int j = 0; j < 16; j++)
        off_out[((size_t)(b * 16 + j)) * Nn + n] = acc[j];
}

// ================= attention (fused KV layout [row,1024]) =================
__global__ void attn_kernel(const float* __restrict__ q, const float* __restrict__ kv,
                            const float* __restrict__ off_t,
                            bf16* __restrict__ aoh, bf16* __restrict__ aol) {
    int gw = (blockIdx.x * blockDim.x + threadIdx.x) >> 5;
    int lane = threadIdx.x & 31;
    if (gw >= MQ * Hh) return;
    int bn = gw / Hh;
    int h  = gw - bn * Hh;
    int b  = bn / Nn;
    int n  = bn - b * Nn;

    float o0 = off_t[((size_t)(b * 16 + h * Pp + 0)) * Nn + n];
    float o1 = off_t[((size_t)(b * 16 + h * Pp + 1)) * Nn + n];
    float t0 = fminf(fmaxf((float)n + o0, 0.f), (float)(2 * Nn - 1));
    float t1 = fminf(fmaxf((float)n + o1, 0.f), (float)(2 * Nn - 1));
    int j0 = (int)t0, j1 = (int)t1;
    int s0 = (j0 >= Nn) ? 1 : 0; int np0 = j0 - s0 * Nn;
    int s1 = (j1 >= Nn) ? 1 : 0; int np1 = j1 - s1 * Nn;

    const float* qb  = q + (size_t)bn * INNERc + h * DHd;
    const float* r0p = kv + ((size_t)(s0 * Bsz + b) * Nn + np0) * (2*INNERc) + h * DHd;
    const float* r1p = kv + ((size_t)(s1 * Bsz + b) * Nn + np1) * (2*INNERc) + h * DHd;

    float qa = qb[lane], qc = qb[lane + 32];
    float d0 = qa * r0p[lane] + qc * r0p[lane + 32];
    float d1 = qa * r1p[lane] + qc * r1p[lane + 32];
    #pragma unroll
    for (int o = 16; o > 0; o >>= 1) {
        d0 += __shfl_xor_sync(0xffffffffu, d0, o);
        d1 += __shfl_xor_sync(0xffffffffu, d1, o);
    }
    const float scale = 0.125f;
    d0 *= scale; d1 *= scale;
    float mx = fmaxf(d0, d1);
    float e0 = __expf(d0 - mx), e1 = __expf(d1 - mx);
    float inv = 1.0f / (e0 + e1);
    float a0 = e0 * inv, a1 = e1 * inv;

    const float* v0p = r0p + INNERc;
    const float* v1p = r1p + INNERc;
    float r0 = a0 * v0p[lane]      + a1 * v1p[lane];
    float r1 = a0 * v0p[lane + 32] + a1 * v1p[lane + 32];
    bf16 hh, ll;
    size_t o_base = (size_t)bn * INNERc + h * DHd;
    bsplit(r0, hh, ll); aoh[o_base + lane]      = hh; aol[o_base + lane]      = ll;
    bsplit(r1, hh, ll); aoh[o_base + lane + 32] = hh; aol[o_base + lane + 32] = ll;
}

// ================= launch =================
extern "C" void kernel_launch(void* const* d_in, const int* in_sizes, int n_in,
                              void* d_out, int out_size) {
    const float* x     = (const float*)d_in[0];
    const float* px    = (const float*)d_in[1];
    const float* lnqg  = (const float*)d_in[2];
    const float* lnqb  = (const float*)d_in[3];
    const float* lnkg  = (const float*)d_in[4];
    const float* lnkb  = (const float*)d_in[5];
    const float* lnvg  = (const float*)d_in[6];
    const float* lnvb  = (const float*)d_in[7];
    const float* Wq    = (const float*)d_in[8];
    const float* Wk    = (const float*)d_in[9];
    const float* bk    = (const float*)d_in[10];
    const float* Wv    = (const float*)d_in[11];
    const float* bv    = (const float*)d_in[12];
    const float* Woff  = (const float*)d_in[13];
    const float* boff  = (const float*)d_in[14];
    const float* Wout  = (const float*)d_in[15];
    const float* bout  = (const float*)d_in[16];

    bf16 *qlnh,*qlnl,*nh,*nl,*aoh,*aol;
    bf16 *wqTh,*wqTl,*wkvTh,*wkvTl,*wouth,*woutl;
    float *qb,*kvb,*biasq,*biaskv;
    cudaGetSymbolAddress((void**)&qlnh, g_qlnh);
    cudaGetSymbolAddress((void**)&qlnl, g_qlnl);
    cudaGetSymbolAddress((void**)&qb,   g_q);
    cudaGetSymbolAddress((void**)&nh,   g_nh);
    cudaGetSymbolAddress((void**)&nl,   g_nl);
    cudaGetSymbolAddress((void**)&kvb,  g_kv);
    cudaGetSymbolAddress((void**)&aoh,  g_aoh);
    cudaGetSymbolAddress((void**)&aol,  g_aol);
    cudaGetSymbolAddress((void**)&wqTh, g_wqTh);
    cudaGetSymbolAddress((void**)&wqTl, g_wqTl);
    cudaGetSymbolAddress((void**)&wkvTh, g_wkvTh);
    cudaGetSymbolAddress((void**)&wkvTl, g_wkvTl);
    cudaGetSymbolAddress((void**)&wouth, g_wouth);
    cudaGetSymbolAddress((void**)&woutl, g_woutl);
    cudaGetSymbolAddress((void**)&biasq,  g_biasq);
    cudaGetSymbolAddress((void**)&biaskv, g_biaskv);

    cudaFuncSetAttribute(bf16x3_gemm<1>, cudaFuncAttributeMaxDynamicSharedMemorySize, GEMM_SMEM);

    // one-time stream/event setup (host objects only; identical work each call)
    static cudaStream_t s2 = nullptr;
    static cudaEvent_t e0 = nullptr, eP = nullptr, eQ = nullptr;
    if (!s2){
        cudaStreamCreateWithFlags(&s2, cudaStreamNonBlocking);
        cudaEventCreateWithFlags(&e0, cudaEventDisableTiming);
        cudaEventCreateWithFlags(&eP, cudaEventDisableTiming);
        cudaEventCreateWithFlags(&eQ, cudaEventDisableTiming);
    }

    float* out_main = (float*)d_out;
    float* out_off  = out_main + (size_t)MQ * DIMc;

    // ---- fork ----
    cudaEventRecord(e0, 0);
    cudaStreamWaitEvent(s2, e0, 0);

    // main stream: prep -> lnkv -> kvGEMM
    prep_kernel<<<1216, dim3(32,8), 0, 0>>>(Wq, lnqg, lnqb, Wk, lnkg, lnkb, bk,
                                            Wv, lnvg, lnvb, bv, Wout,
                                            wqTh, wqTl, wkvTh, wkvTl, wouth, woutl,
                                            biasq, biaskv);
    cudaEventRecord(eP, 0);
    lnkv_kernel<<<MKV, 256, 0, 0>>>(x, px, nh, nl);
    bf16x3_gemm<1><<<dim3(2*INNERc/128, MKV/128), 256, GEMM_SMEM, 0>>>(nh, nl, wkvTh, wkvTl, biaskv, kvb, 2*INNERc, DIMc);

    // side stream: lnq -> (wait prep) -> qGEMM -> off
    lnq_kernel<<<MQ, 256, 0, s2>>>(x, px, qlnh, qlnl);
    cudaStreamWaitEvent(s2, eP, 0);
    bf16x3_gemm<1><<<dim3(INNERc/128, MQ/128), 256, GEMM_SMEM, s2>>>(qlnh, qlnl, wqTh, wqTl, biasq, qb, INNERc, INNERc);
    off_kernel<<<MQ/128, 128, 0, s2>>>(qb, Woff, boff, out_off);
    cudaEventRecord(eQ, s2);

    // ---- join ----
    cudaStreamWaitEvent(0, eQ, 0);
    attn_kernel<<<(MQ*Hh)/8, 256, 0, 0>>>(qb, kvb, out_off, aoh, aol);
    bf16x3_gemm<1><<<dim3(DIMc/128, MQ/128), 256, GEMM_SMEM, 0>>>(aoh, aol, wouth, woutl, bout, out_main, DIMc, INNERc);
}

// round 11
// speedup vs baseline: 1.3718x; 1.3718x over previous
#include <cuda_runtime.h>
#include <cuda_bf16.h>
#include <cstdint>
#include <math.h>

#define Bsz 4
#define Nn 4096
#define DIMc 256
#define Hh 8
#define DHd 64
#define Pp 2
#define INNERc 512
#define MQ (Bsz*Nn)      /* 16384 */
#define MKV (2*Bsz*Nn)   /* 32768 */

typedef __nv_bfloat16 bf16;

// ---------------- scratch (device globals) ----------------
__device__ bf16  g_qlnh[MQ * INNERc];
__device__ bf16  g_qlnl[MQ * INNERc];
__device__ float g_q   [MQ * INNERc];
__device__ bf16  g_nh  [MKV * DIMc];
__device__ bf16  g_nl  [MKV * DIMc];
__device__ float g_kv  [MKV * 2 * INNERc];
__device__ bf16  g_aoh [MQ * INNERc];
__device__ bf16  g_aol [MQ * INNERc];
__device__ bf16  g_wqTh[INNERc * INNERc];
__device__ bf16  g_wqTl[INNERc * INNERc];
__device__ bf16  g_wkvTh[2 * INNERc * DIMc];
__device__ bf16  g_wkvTl[2 * INNERc * DIMc];
__device__ bf16  g_wouth[DIMc * INNERc];
__device__ bf16  g_woutl[DIMc * INNERc];
__device__ float g_biasq [INNERc];
__device__ float g_biaskv[2 * INNERc];

// ================= helpers =================
__device__ __forceinline__ uint32_t smem_u32(const void* p){
    uint32_t a;
    asm("{ .reg .u64 t; cvta.to.shared.u64 t, %1; cvt.u32.u64 %0, t; }" : "=r"(a) : "l"(p));
    return a;
}
__device__ __forceinline__ void bsplit(float v, bf16& h, bf16& l){
    h = __float2bfloat16(v);
    l = __float2bfloat16(v - __bfloat162float(h));
}
__device__ __forceinline__ void mma_bf16(float d[4], const uint32_t a[4], const uint32_t b[2]){
    asm volatile("mma.sync.aligned.m16n8k16.row.col.f32.bf16.bf16.f32 "
        "{%0,%1,%2,%3}, {%4,%5,%6,%7}, {%8,%9}, {%0,%1,%2,%3};"
        : "+f"(d[0]),"+f"(d[1]),"+f"(d[2]),"+f"(d[3])
        : "r"(a[0]),"r"(a[1]),"r"(a[2]),"r"(a[3]),"r"(b[0]),"r"(b[1]));
}
__device__ __forceinline__ void ldsm4(uint32_t r[4], uint32_t addr){
    asm volatile("ldmatrix.sync.aligned.m8n8.x4.shared.b16 {%0,%1,%2,%3}, [%4];"
        : "=r"(r[0]),"=r"(r[1]),"=r"(r[2]),"=r"(r[3]) : "r"(addr));
}
__device__ __forceinline__ void cp16(uint32_t dst, const void* src){
    asm volatile("cp.async.cg.shared.global [%0], [%1], 16;" :: "r"(dst), "l"(src));
}
// swizzled byte offset within a plane: row (0..127) has 64B = 4 x 16B slots
__device__ __forceinline__ uint32_t swz(int r, int s){
    return (uint32_t)(r * 64 + ((s ^ ((r >> 1) & 3)) << 4));
}

// ================= bf16x3 tensor-core GEMM (R9, unchanged) =================
#define TILE_B 8192
#define STAGE_B 32768
#define GEMM_SMEM (3*STAGE_B)

template<int HAS_BIAS>
__global__ void __launch_bounds__(256, 2)
bf16x3_gemm(const bf16* __restrict__ Ah, const bf16* __restrict__ Al,
            const bf16* __restrict__ Bh, const bf16* __restrict__ Bl,
            const float* __restrict__ bias, float* __restrict__ C,
            int Ntot, int K)
{
    extern __shared__ char smem[];
    const uint32_t sb = smem_u32(smem);
    const int tid = threadIdx.x, lane = tid & 31, wid = tid >> 5;
    const int wm = wid >> 2, wn = wid & 3;
    const int bm = blockIdx.y * 128, bn = blockIdx.x * 128;
    const int NC = K >> 5;

    const int lr  = tid >> 2;
    const int lcc = tid & 3;
    const uint32_t w0 = swz(lr, lcc), w1 = swz(lr + 64, lcc);

    uint32_t aoff[2][4], boff[2][2];
    #pragma unroll
    for (int ks = 0; ks < 2; ks++){
        const int slot = (lane >> 4) + ks * 2;
        #pragma unroll
        for (int i = 0; i < 4; i++)
            aoff[ks][i] = swz(wm*64 + i*16 + (lane & 15), slot);
        #pragma unroll
        for (int jp = 0; jp < 2; jp++)
            boff[ks][jp] = 2*TILE_B + swz(wn*32 + jp*16 + (lane & 15), slot);
    }

    auto load_stage = [&](int buf, int kc){
        uint32_t base = sb + buf * STAGE_B;
        size_t ao = (size_t)(bm + lr) * K + kc + lcc * 8;
        size_t bo = (size_t)(bn + lr) * K + kc + lcc * 8;
        size_t row64 = (size_t)64 * K;
        cp16(base + w0,            Ah + ao);
        cp16(base + w1,            Ah + ao + row64);
        cp16(base + TILE_B + w0,   Al + ao);
        cp16(base + TILE_B + w1,   Al + ao + row64);
        cp16(base + 2*TILE_B + w0, Bh + bo);
        cp16(base + 2*TILE_B + w1, Bh + bo + row64);
        cp16(base + 3*TILE_B + w0, Bl + bo);
        cp16(base + 3*TILE_B + w1, Bl + bo + row64);
        asm volatile("cp.async.commit_group;" ::: "memory");
    };

    float acc[4][4][4] = {};

    auto compute = [&](int buf){
        uint32_t base = sb + buf * STAGE_B;
        #pragma unroll
        for (int ks = 0; ks < 2; ks++){
            uint32_t BH[4][2], BL[4][2];
            #pragma unroll
            for (int jp = 0; jp < 2; jp++){
                uint32_t a = base + boff[ks][jp];
                uint32_t r4[4];
                ldsm4(r4, a);
                BH[jp*2][0]=r4[0]; BH[jp*2+1][0]=r4[1]; BH[jp*2][1]=r4[2]; BH[jp*2+1][1]=r4[3];
                ldsm4(r4, a + TILE_B);
                BL[jp*2][0]=r4[0]; BL[jp*2+1][0]=r4[1]; BL[jp*2][1]=r4[2]; BL[jp*2+1][1]=r4[3];
            }
            #pragma unroll
            for (int i = 0; i < 4; i++){
                uint32_t a = base + aoff[ks][i];
                uint32_t ah[4], al_[4];
                ldsm4(ah,  a);
                ldsm4(al_, a + TILE_B);
                #pragma unroll
                for (int j = 0; j < 4; j++) mma_bf16(acc[i][j], ah,  BH[j]);
                #pragma unroll
                for (int j = 0; j < 4; j++) mma_bf16(acc[i][j], ah,  BL[j]);
                #pragma unroll
                for (int j = 0; j < 4; j++) mma_bf16(acc[i][j], al_, BH[j]);
            }
        }
    };

    load_stage(0, 0);
    load_stage(1, 32);

    for (int c = 0; c < NC; c++){
        if (c < NC - 1) asm volatile("cp.async.wait_group 1;" ::: "memory");
        else            asm volatile("cp.async.wait_group 0;" ::: "memory");
        __syncthreads();
        if (c + 2 < NC) load_stage((c + 2) % 3, (c + 2) * 32);
        compute(c % 3);
    }

    #pragma unroll
    for (int i = 0; i < 4; i++){
        int r0 = bm + wm*64 + i*16 + (lane >> 2);
        #pragma unroll
        for (int j = 0; j < 4; j++){
            int c0 = bn + wn*32 + j*8 + (lane & 3)*2;
            float b0 = 0.f, b1 = 0.f;
            if (HAS_BIAS){ b0 = bias[c0]; b1 = bias[c0+1]; }
            *(float2*)(C + (size_t)r0 * Ntot + c0)     = make_float2(acc[i][j][0]+b0, acc[i][j][1]+b1);
            *(float2*)(C + (size_t)(r0+8) * Ntot + c0) = make_float2(acc[i][j][2]+b0, acc[i][j][3]+b1);
        }
    }
}

// ================= merged weight prep (single launch) =================
__device__ __forceinline__ void tss_body(const float* in, const float* g,
                                         bf16* oh, bf16* ol, int R, int C,
                                         int bx, int by, int tx, int ty){
    __shared__ float tile[32][33];
    int c0 = bx * 32, r0 = by * 32;
    #pragma unroll
    for (int i = 0; i < 32; i += 8){
        int r = r0 + ty + i;
        tile[ty + i][tx] = in[(size_t)r * C + c0 + tx] * g[r];
    }
    __syncthreads();
    #pragma unroll
    for (int i = 0; i < 32; i += 8){
        float v = tile[tx][ty + i];
        bf16 h, l; bsplit(v, h, l);
        size_t o = (size_t)(c0 + ty + i) * R + r0 + tx;
        oh[o] = h; ol[o] = l;
    }
}
__device__ __forceinline__ void fold_body(const float* W, const float* beta,
                                          const float* base, float* out,
                                          int K, int N, int n, int lane){
    float s = 0.f;
    for (int k = lane; k < K; k += 32) s += beta[k] * W[(size_t)k * N + n];
    #pragma unroll
    for (int o = 16; o > 0; o >>= 1) s += __shfl_xor_sync(0xffffffffu, s, o);
    if (lane == 0) out[n] = s + (base ? base[n] : 0.f);
}

__global__ void prep_kernel(const float* __restrict__ Wq, const float* __restrict__ lnqg, const float* __restrict__ lnqb,
                            const float* __restrict__ Wk, const float* __restrict__ lnkg, const float* __restrict__ lnkb, const float* __restrict__ bk,
                            const float* __restrict__ Wv, const float* __restrict__ lnvg, const float* __restrict__ lnvb, const float* __restrict__ bv,
                            const float* __restrict__ Wout,
                            bf16* __restrict__ wqTh, bf16* __restrict__ wqTl,
                            bf16* __restrict__ wkvTh, bf16* __restrict__ wkvTl,
                            bf16* __restrict__ wouth, bf16* __restrict__ woutl,
                            float* __restrict__ biasq, float* __restrict__ biaskv){
    int id = blockIdx.x;
    int tx = threadIdx.x, ty = threadIdx.y;           // (32, 8)
    if (id < 256){
        tss_body(Wq, lnqg, wqTh, wqTl, INNERc, INNERc, id & 15, id >> 4, tx, ty);
    } else if (id < 384){
        int l = id - 256;
        tss_body(Wk, lnkg, wkvTh, wkvTl, DIMc, INNERc, l & 15, l >> 4, tx, ty);
    } else if (id < 512){
        int l = id - 384;
        tss_body(Wv, lnvg, wkvTh + (size_t)INNERc*DIMc, wkvTl + (size_t)INNERc*DIMc,
                 DIMc, INNERc, l & 15, l >> 4, tx, ty);
    } else if (id < 1024){
        int i = (id - 512) * 256 + ty * 32 + tx;
        bf16 h, l; bsplit(Wout[i], h, l);
        wouth[i] = h; woutl[i] = l;
    } else if (id < 1088){
        int n = (id - 1024) * 8 + ty;
        fold_body(Wq, lnqb, nullptr, biasq, INNERc, INNERc, n, tx);
    } else if (id < 1152){
        int n = (id - 1088) * 8 + ty;
        fold_body(Wk, lnkb, bk, biaskv, DIMc, INNERc, n, tx);
    } else {
        int n = (id - 1152) * 8 + ty;
        fold_body(Wv, lnvb, bv, biaskv + INNERc, DIMc, INNERc, n, tx);
    }
}

// ================= merged warp-per-row LayerNorm (lnq + lnkv) =================
// warps [0, MQ)        : LN over concat(x,px) (512) -> qlnh/qlnl
// warps [MQ, MQ+MKV)   : LN over kv rows (256)      -> nh/nl
__device__ __forceinline__ uint4 pack8(const float* v, float mean, float rstd){
    uint32_t p[4];
    #pragma unroll
    for (int i = 0; i < 4; i++){
        bf16 h0, l0, h1, l1;
        bsplit((v[2*i]   - mean) * rstd, h0, l0);
        bsplit((v[2*i+1] - mean) * rstd, h1, l1);
        p[i] = (uint32_t)__bfloat16_as_ushort(h0) | ((uint32_t)__bfloat16_as_ushort(h1) << 16);
        // stash lo in high half via second pass below — handled by caller twice
        (void)l0; (void)l1;
    }
    return make_uint4(p[0], p[1], p[2], p[3]);
}

__global__ void ln_all_kernel(const float* __restrict__ x, const float* __restrict__ px,
                              bf16* __restrict__ qoh, bf16* __restrict__ qol,
                              bf16* __restrict__ nh, bf16* __restrict__ nl){
    int gw = (blockIdx.x * blockDim.x + threadIdx.x) >> 5;
    int lane = threadIdx.x & 31;
    if (gw < MQ){
        size_t base = (size_t)gw * DIMc + lane * 8;
        float4 a0 = *(const float4*)(x  + base);
        float4 a1 = *(const float4*)(x  + base + 4);
        float4 b0 = *(const float4*)(px + base);
        float4 b1 = *(const float4*)(px + base + 4);
        float va[8] = {a0.x,a0.y,a0.z,a0.w,a1.x,a1.y,a1.z,a1.w};
        float vb[8] = {b0.x,b0.y,b0.z,b0.w,b1.x,b1.y,b1.z,b1.w};
        float s = 0.f, ss = 0.f;
        #pragma unroll
        for (int i = 0; i < 8; i++){ s += va[i] + vb[i]; ss += va[i]*va[i] + vb[i]*vb[i]; }
        #pragma unroll
        for (int o = 16; o > 0; o >>= 1){
            s  += __shfl_xor_sync(0xffffffffu, s, o);
            ss += __shfl_xor_sync(0xffffffffu, ss, o);
        }
        float mean = s * (1.0f/512.0f);
        float var  = ss * (1.0f/512.0f) - mean*mean;
        float rstd = rsqrtf(var + 1e-5f);
        uint32_t ph[4], pl[4];
        // x-half
        #pragma unroll
        for (int i = 0; i < 4; i++){
            bf16 h0,l0,h1,l1;
            bsplit((va[2*i]   - mean)*rstd, h0, l0);
            bsplit((va[2*i+1] - mean)*rstd, h1, l1);
            ph[i] = (uint32_t)__bfloat16_as_ushort(h0) | ((uint32_t)__bfloat16_as_ushort(h1) << 16);
            pl[i] = (uint32_t)__bfloat16_as_ushort(l0) | ((uint32_t)__bfloat16_as_ushort(l1) << 16);
        }
        size_t ob = (size_t)gw * INNERc + lane * 8;
        *(uint4*)(qoh + ob) = make_uint4(ph[0],ph[1],ph[2],ph[3]);
        *(uint4*)(qol + ob) = make_uint4(pl[0],pl[1],pl[2],pl[3]);
        // px-half
        #pragma unroll
        for (int i = 0; i < 4; i++){
            bf16 h0,l0,h1,l1;
            bsplit((vb[2*i]   - mean)*rstd, h0, l0);
            bsplit((vb[2*i+1] - mean)*rstd, h1, l1);
            ph[i] = (uint32_t)__bfloat16_as_ushort(h0) | ((uint32_t)__bfloat16_as_ushort(h1) << 16);
            pl[i] = (uint32_t)__bfloat16_as_ushort(l0) | ((uint32_t)__bfloat16_as_ushort(l1) << 16);
        }
        *(uint4*)(qoh + ob + 256) = make_uint4(ph[0],ph[1],ph[2],ph[3]);
        *(uint4*)(qol + ob + 256) = make_uint4(pl[0],pl[1],pl[2],pl[3]);
    } else {
        int row = gw - MQ;                        // 0..MKV-1
        const float* src = (row < MQ) ? x : px;
        int r2 = (row < MQ) ? row : row - MQ;
        size_t base = (size_t)r2 * DIMc + lane * 8;
        float4 a0 = *(const float4*)(src + base);
        float4 a1 = *(const float4*)(src + base + 4);
        float v[8] = {a0.x,a0.y,a0.z,a0.w,a1.x,a1.y,a1.z,a1.w};
        float s = 0.f, ss = 0.f;
        #pragma unroll
        for (int i = 0; i < 8; i++){ s += v[i]; ss += v[i]*v[i]; }
        #pragma unroll
        for (int o = 16; o > 0; o >>= 1){
            s  += __shfl_xor_sync(0xffffffffu, s, o);
            ss += __shfl_xor_sync(0xffffffffu, ss, o);
        }
        float mean = s * (1.0f/256.0f);
        float var  = ss * (1.0f/256.0f) - mean*mean;
        float rstd = rsqrtf(var + 1e-5f);
        uint32_t ph[4], pl[4];
        #pragma unroll
        for (int i = 0; i < 4; i++){
            bf16 h0,l0,h1,l1;
            bsplit((v[2*i]   - mean)*rstd, h0, l0);
            bsplit((v[2*i+1] - mean)*rstd, h1, l1);
            ph[i] = (uint32_t)__bfloat16_as_ushort(h0) | ((uint32_t)__bfloat16_as_ushort(h1) << 16);
            pl[i] = (uint32_t)__bfloat16_as_ushort(l0) | ((uint32_t)__bfloat16_as_ushort(l1) << 16);
        }
        size_t ob = (size_t)row * DIMc + lane * 8;
        *(uint4*)(nh + ob) = make_uint4(ph[0],ph[1],ph[2],ph[3]);
        *(uint4*)(nl + ob) = make_uint4(pl[0],pl[1],pl[2],pl[3]);
    }
}

// ============ offsets projection (fp32) — writes transposed (B,H,P,N) ============
__global__ void off_kernel(const float* __restrict__ q, const float* __restrict__ Woff,
                           const float* __restrict__ boff, float* __restrict__ off_out) {
    __shared__ float w[16][INNERc];
    int tid = threadIdx.x;
    for (int i = tid; i < 16 * INNERc; i += 128) w[i >> 9][i & 511] = Woff[i];
    __syncthreads();
    int m = blockIdx.x * 128 + tid;        // b*N + n
    const float* qr = q + (size_t)m * INNERc;
    float acc[16];
    #pragma unroll
    for (int j = 0; j < 16; j++) acc[j] = boff[j];
    for (int k0 = 0; k0 < INNERc; k0 += 4){
        float4 qv = *(const float4*)(qr + k0);
        #pragma unroll
        for (int j = 0; j < 16; j++)
            acc[j] += qv.x * w[j][k0] + qv.y * w[j][k0+1] + qv.z * w[j][k0+2] + qv.w * w[j][k0+3];
    }
    int b = m >> 12, n = m & 4095;
    #pragma unroll
    for (int j = 0; j < 16; j++)
        off_out[((size_t)(b * 16 + j)) * Nn + n] = acc[j];
}

// ================= attention (fused KV layout [row,1024]) =================
__global__ void attn_kernel(const float* __restrict__ q, const float* __restrict__ kv,
                            const float* __restrict__ off_t,
                            bf16* __restrict__ aoh, bf16* __restrict__ aol) {
    int gw = (blockIdx.x * blockDim.x + threadIdx.x) >> 5;
    int lane = threadIdx.x & 31;
    if (gw >= MQ * Hh) return;
    int bn = gw / Hh;
    int h  = gw - bn * Hh;
    int b  = bn / Nn;
    int n  = bn - b * Nn;

    float o0 = off_t[((size_t)(b * 16 + h * Pp + 0)) * Nn + n];
    float o1 = off_t[((size_t)(b * 16 + h * Pp + 1)) * Nn + n];
    float t0 = fminf(fmaxf((float)n + o0, 0.f), (float)(2 * Nn - 1));
    float t1 = fminf(fmaxf((float)n + o1, 0.f), (float)(2 * Nn - 1));
    int j0 = (int)t0, j1 = (int)t1;
    int s0 = (j0 >= Nn) ? 1 : 0; int np0 = j0 - s0 * Nn;
    int s1 = (j1 >= Nn) ? 1 : 0; int np1 = j1 - s1 * Nn;

    const float* qb  = q + (size_t)bn * INNERc + h * DHd;
    const float* r0p = kv + ((size_t)(s0 * Bsz + b) * Nn + np0) * (2*INNERc) + h * DHd;
    const float* r1p = kv + ((size_t)(s1 * Bsz + b) * Nn + np1) * (2*INNERc) + h * DHd;

    float qa = qb[lane], qc = qb[lane + 32];
    float d0 = qa * r0p[lane] + qc * r0p[lane + 32];
    float d1 = qa * r1p[lane] + qc * r1p[lane + 32];
    #pragma unroll
    for (int o = 16; o > 0; o >>= 1) {
        d0 += __shfl_xor_sync(0xffffffffu, d0, o);
        d1 += __shfl_xor_sync(0xffffffffu, d1, o);
    }
    const float scale = 0.125f;
    d0 *= scale; d1 *= scale;
    float mx = fmaxf(d0, d1);
    float e0 = __expf(d0 - mx), e1 = __expf(d1 - mx);
    float inv = 1.0f / (e0 + e1);
    float a0 = e0 * inv, a1 = e1 * inv;

    const float* v0p = r0p + INNERc;
    const float* v1p = r1p + INNERc;
    float r0 = a0 * v0p[lane]      + a1 * v1p[lane];
    float r1 = a0 * v0p[lane + 32] + a1 * v1p[lane + 32];
    bf16 hh, ll;
    size_t o_base = (size_t)bn * INNERc + h * DHd;
    bsplit(r0, hh, ll); aoh[o_base + lane]      = hh; aol[o_base + lane]      = ll;
    bsplit(r1, hh, ll); aoh[o_base + lane + 32] = hh; aol[o_base + lane + 32] = ll;
}

// ================= launch =================
extern "C" void kernel_launch(void* const* d_in, const int* in_sizes, int n_in,
                              void* d_out, int out_size) {
    const float* x     = (const float*)d_in[0];
    const float* px    = (const float*)d_in[1];
    const float* lnqg  = (const float*)d_in[2];
    const float* lnqb  = (const float*)d_in[3];
    const float* lnkg  = (const float*)d_in[4];
    const float* lnkb  = (const float*)d_in[5];
    const float* lnvg  = (const float*)d_in[6];
    const float* lnvb  = (const float*)d_in[7];
    const float* Wq    = (const float*)d_in[8];
    const float* Wk    = (const float*)d_in[9];
    const float* bk    = (const float*)d_in[10];
    const float* Wv    = (const float*)d_in[11];
    const float* bv    = (const float*)d_in[12];
    const float* Woff  = (const float*)d_in[13];
    const float* boff  = (const float*)d_in[14];
    const float* Wout  = (const float*)d_in[15];
    const float* bout  = (const float*)d_in[16];

    bf16 *qlnh,*qlnl,*nh,*nl,*aoh,*aol;
    bf16 *wqTh,*wqTl,*wkvTh,*wkvTl,*wouth,*woutl;
    float *qb,*kvb,*biasq,*biaskv;
    cudaGetSymbolAddress((void**)&qlnh, g_qlnh);
    cudaGetSymbolAddress((void**)&qlnl, g_qlnl);
    cudaGetSymbolAddress((void**)&qb,   g_q);
    cudaGetSymbolAddress((void**)&nh,   g_nh);
    cudaGetSymbolAddress((void**)&nl,   g_nl);
    cudaGetSymbolAddress((void**)&kvb,  g_kv);
    cudaGetSymbolAddress((void**)&aoh,  g_aoh);
    cudaGetSymbolAddress((void**)&aol,  g_aol);
    cudaGetSymbolAddress((void**)&wqTh, g_wqTh);
    cudaGetSymbolAddress((void**)&wqTl, g_wqTl);
    cudaGetSymbolAddress((void**)&wkvTh, g_wkvTh);
    cudaGetSymbolAddress((void**)&wkvTl, g_wkvTl);
    cudaGetSymbolAddress((void**)&wouth, g_wouth);
    cudaGetSymbolAddress((void**)&woutl, g_woutl);
    cudaGetSymbolAddress((void**)&biasq,  g_biasq);
    cudaGetSymbolAddress((void**)&biaskv, g_biaskv);

    cudaFuncSetAttribute(bf16x3_gemm<1>, cudaFuncAttributeMaxDynamicSharedMemorySize, GEMM_SMEM);

    float* out_main = (float*)d_out;
    float* out_off  = out_main + (size_t)MQ * DIMc;

    // 0: all weight prep
    prep_kernel<<<1216, dim3(32,8)>>>(Wq, lnqg, lnqb, Wk, lnkg, lnkb, bk,
                                      Wv, lnvg, lnvb, bv, Wout,
                                      wqTh, wqTl, wkvTh, wkvTl, wouth, woutl,
                                      biasq, biaskv);
    // 1: merged LN (warp per row): (MQ + MKV) warps, 8 per block
    ln_all_kernel<<<(MQ + MKV)/8, 256>>>(x, px, qlnh, qlnl, nh, nl);

    // 2: kv = nrm @ [foldedWk | foldedWv] + biaskv
    bf16x3_gemm<1><<<dim3(2*INNERc/128, MKV/128), 256, GEMM_SMEM>>>(nh, nl, wkvTh, wkvTl, biaskv, kvb, 2*INNERc, DIMc);
    // 3: q = nrm_q @ foldedWq + biasq
    bf16x3_gemm<1><<<dim3(INNERc/128, MQ/128),  256, GEMM_SMEM>>>(qlnh, qlnl, wqTh, wqTl, biasq, qb, INNERc, INNERc);

    // 4,5: offsets + attention
    off_kernel<<<MQ/128, 128>>>(qb, Woff, boff, out_off);
    attn_kernel<<<(MQ*Hh)/8, 256>>>(qb, kvb, out_off, aoh, aol);

    // 6: out = ao @ Wout^T + bout
    bf16x3_gemm<1><<<dim3(DIMc/128, MQ/128), 256, GEMM_SMEM>>>(aoh, aol, wouth, woutl, bout, out_main, DIMc, INNERc);
}

// round 12
// speedup vs baseline: 1.3782x; 1.0047x over previous
#include <cuda_runtime.h>
#include <cuda_bf16.h>
#include <cstdint>
#include <math.h>

#define Bsz 4
#define Nn 4096
#define DIMc 256
#define Hh 8
#define DHd 64
#define Pp 2
#define INNERc 512
#define MQ (Bsz*Nn)      /* 16384 */
#define MKV (2*Bsz*Nn)   /* 32768 */

typedef __nv_bfloat16 bf16;

// ---------------- scratch (device globals) ----------------
__device__ bf16  g_qlnh[MQ * INNERc];
__device__ bf16  g_qlnl[MQ * INNERc];
__device__ float g_q   [MQ * INNERc];
__device__ bf16  g_nh  [MKV * DIMc];
__device__ bf16  g_nl  [MKV * DIMc];
__device__ float g_kv  [MKV * 2 * INNERc];
__device__ bf16  g_aoh [MQ * INNERc];
__device__ bf16  g_aol [MQ * INNERc];
__device__ bf16  g_wqTh[INNERc * INNERc];
__device__ bf16  g_wqTl[INNERc * INNERc];
__device__ bf16  g_wkvTh[2 * INNERc * DIMc];
__device__ bf16  g_wkvTl[2 * INNERc * DIMc];
__device__ bf16  g_wouth[DIMc * INNERc];
__device__ bf16  g_woutl[DIMc * INNERc];
__device__ float g_biasq [INNERc];
__device__ float g_biaskv[2 * INNERc];

// ================= helpers =================
__device__ __forceinline__ uint32_t smem_u32(const void* p){
    uint32_t a;
    asm("{ .reg .u64 t; cvta.to.shared.u64 t, %1; cvt.u32.u64 %0, t; }" : "=r"(a) : "l"(p));
    return a;
}
__device__ __forceinline__ void bsplit(float v, bf16& h, bf16& l){
    h = __float2bfloat16(v);
    l = __float2bfloat16(v - __bfloat162float(h));
}
__device__ __forceinline__ void mma_bf16(float d[4], const uint32_t a[4], const uint32_t b[2]){
    asm volatile("mma.sync.aligned.m16n8k16.row.col.f32.bf16.bf16.f32 "
        "{%0,%1,%2,%3}, {%4,%5,%6,%7}, {%8,%9}, {%0,%1,%2,%3};"
        : "+f"(d[0]),"+f"(d[1]),"+f"(d[2]),"+f"(d[3])
        : "r"(a[0]),"r"(a[1]),"r"(a[2]),"r"(a[3]),"r"(b[0]),"r"(b[1]));
}
__device__ __forceinline__ void ldsm4(uint32_t r[4], uint32_t addr){
    asm volatile("ldmatrix.sync.aligned.m8n8.x4.shared.b16 {%0,%1,%2,%3}, [%4];"
        : "=r"(r[0]),"=r"(r[1]),"=r"(r[2]),"=r"(r[3]) : "r"(addr));
}
__device__ __forceinline__ void cp16(uint32_t dst, const void* src){
    asm volatile("cp.async.cg.shared.global [%0], [%1], 16;" :: "r"(dst), "l"(src));
}
// swizzled byte offset within a plane: row has 64B = 4 x 16B slots
__device__ __forceinline__ uint32_t swz(int r, int s){
    return (uint32_t)(r * 64 + ((s ^ ((r >> 1) & 3)) << 4));
}

// ================= bf16x3 tensor-core GEMM =================
// C[M,Ntot] = (Ah+Al)[M,K] @ (Bh+Bl)[Ntot,K]^T (+bias), x3 terms.
// 256 thr, tile 128xNT, K-chunk 32, 3-stage cp.async (depth 2),
// swizzled 64B rows, 2 CTAs/SM, one barrier per chunk.
#define TILE_A 8192

template<int HAS_BIAS, int NT>
__global__ void __launch_bounds__(256, 2)
bf16x3_gemm(const bf16* __restrict__ Ah, const bf16* __restrict__ Al,
            const bf16* __restrict__ Bh, const bf16* __restrict__ Bl,
            const float* __restrict__ bias, float* __restrict__ C,
            int Ntot, int K)
{
    constexpr int NJ  = NT / 32;          // 8-wide j units per warp
    constexpr int NJP = NT / 64;          // ldsm pair iterations
    constexpr int TILE_BP = NT * 64;      // bytes per B plane
    constexpr int STAGE = 2*TILE_A + 2*TILE_BP;

    extern __shared__ char smem[];
    const uint32_t sb = smem_u32(smem);
    const int tid = threadIdx.x, lane = tid & 31, wid = tid >> 5;
    const int wm = wid >> 2, wn = wid & 3;
    const int bm = blockIdx.y * 128, bn = blockIdx.x * NT;
    const int NC = K >> 5;

    const int lr  = tid >> 2;
    const int lcc = tid & 3;
    const uint32_t w0 = swz(lr, lcc), w1 = swz(lr + 64, lcc);

    uint32_t aoff[2][4], boff[2][NJP];
    #pragma unroll
    for (int ks = 0; ks < 2; ks++){
        const int slot = (lane >> 4) + ks * 2;
        #pragma unroll
        for (int i = 0; i < 4; i++)
            aoff[ks][i] = swz(wm*64 + i*16 + (lane & 15), slot);
        #pragma unroll
        for (int jp = 0; jp < NJP; jp++)
            boff[ks][jp] = 2*TILE_A + swz(wn*(NT/4) + jp*16 + (lane & 15), slot);
    }

    auto load_stage = [&](int buf, int kc){
        uint32_t base = sb + buf * STAGE;
        size_t ao = (size_t)(bm + lr) * K + kc + lcc * 8;
        size_t bo = (size_t)(bn + lr) * K + kc + lcc * 8;
        size_t row64 = (size_t)64 * K;
        cp16(base + w0,           Ah + ao);
        cp16(base + w1,           Ah + ao + row64);
        cp16(base + TILE_A + w0,  Al + ao);
        cp16(base + TILE_A + w1,  Al + ao + row64);
        cp16(base + 2*TILE_A + w0,            Bh + bo);
        cp16(base + 2*TILE_A + TILE_BP + w0,  Bl + bo);
        if (NT == 128){
            cp16(base + 2*TILE_A + w1,           Bh + bo + row64);
            cp16(base + 2*TILE_A + TILE_BP + w1, Bl + bo + row64);
        }
        asm volatile("cp.async.commit_group;" ::: "memory");
    };

    float acc[4][NJ][4] = {};

    auto compute = [&](int buf){
        uint32_t base = sb + buf * STAGE;
        #pragma unroll
        for (int ks = 0; ks < 2; ks++){
            uint32_t BH[NJ][2], BL[NJ][2];
            #pragma unroll
            for (int jp = 0; jp < NJP; jp++){
                uint32_t a = base + boff[ks][jp];
                uint32_t r4[4];
                ldsm4(r4, a);
                BH[jp*2][0]=r4[0]; BH[jp*2+1][0]=r4[1]; BH[jp*2][1]=r4[2]; BH[jp*2+1][1]=r4[3];
                ldsm4(r4, a + TILE_BP);
                BL[jp*2][0]=r4[0]; BL[jp*2+1][0]=r4[1]; BL[jp*2][1]=r4[2]; BL[jp*2+1][1]=r4[3];
            }
            #pragma unroll
            for (int i = 0; i < 4; i++){
                uint32_t a = base + aoff[ks][i];
                uint32_t ah[4], al_[4];
                ldsm4(ah,  a);
                ldsm4(al_, a + TILE_A);
                #pragma unroll
                for (int j = 0; j < NJ; j++) mma_bf16(acc[i][j], ah,  BH[j]);
                #pragma unroll
                for (int j = 0; j < NJ; j++) mma_bf16(acc[i][j], ah,  BL[j]);
                #pragma unroll
                for (int j = 0; j < NJ; j++) mma_bf16(acc[i][j], al_, BH[j]);
            }
        }
    };

    load_stage(0, 0);
    load_stage(1, 32);

    for (int c = 0; c < NC; c++){
        if (c < NC - 1) asm volatile("cp.async.wait_group 1;" ::: "memory");
        else            asm volatile("cp.async.wait_group 0;" ::: "memory");
        __syncthreads();
        if (c + 2 < NC) load_stage((c + 2) % 3, (c + 2) * 32);
        compute(c % 3);
    }

    #pragma unroll
    for (int i = 0; i < 4; i++){
        int r0 = bm + wm*64 + i*16 + (lane >> 2);
        #pragma unroll
        for (int j = 0; j < NJ; j++){
            int c0 = bn + wn*(NT/4) + j*8 + (lane & 3)*2;
            float b0 = 0.f, b1 = 0.f;
            if (HAS_BIAS){ b0 = bias[c0]; b1 = bias[c0+1]; }
            *(float2*)(C + (size_t)r0 * Ntot + c0)     = make_float2(acc[i][j][0]+b0, acc[i][j][1]+b1);
            *(float2*)(C + (size_t)(r0+8) * Ntot + c0) = make_float2(acc[i][j][2]+b0, acc[i][j][3]+b1);
        }
    }
}

#define GEMM_SMEM_128 (3*(2*TILE_A + 2*128*64))
#define GEMM_SMEM_64  (3*(2*TILE_A + 2*64*64))

// ================= merged weight prep (single launch) =================
__device__ __forceinline__ void tss_body(const float* in, const float* g,
                                         bf16* oh, bf16* ol, int R, int C,
                                         int bx, int by, int tx, int ty){
    __shared__ float tile[32][33];
    int c0 = bx * 32, r0 = by * 32;
    #pragma unroll
    for (int i = 0; i < 32; i += 8){
        int r = r0 + ty + i;
        tile[ty + i][tx] = in[(size_t)r * C + c0 + tx] * g[r];
    }
    __syncthreads();
    #pragma unroll
    for (int i = 0; i < 32; i += 8){
        float v = tile[tx][ty + i];
        bf16 h, l; bsplit(v, h, l);
        size_t o = (size_t)(c0 + ty + i) * R + r0 + tx;
        oh[o] = h; ol[o] = l;
    }
}
__device__ __forceinline__ void fold_body(const float* W, const float* beta,
                                          const float* base, float* out,
                                          int K, int N, int n, int lane){
    float s = 0.f;
    for (int k = lane; k < K; k += 32) s += beta[k] * W[(size_t)k * N + n];
    #pragma unroll
    for (int o = 16; o > 0; o >>= 1) s += __shfl_xor_sync(0xffffffffu, s, o);
    if (lane == 0) out[n] = s + (base ? base[n] : 0.f);
}

__global__ void prep_kernel(const float* __restrict__ Wq, const float* __restrict__ lnqg, const float* __restrict__ lnqb,
                            const float* __restrict__ Wk, const float* __restrict__ lnkg, const float* __restrict__ lnkb, const float* __restrict__ bk,
                            const float* __restrict__ Wv, const float* __restrict__ lnvg, const float* __restrict__ lnvb, const float* __restrict__ bv,
                            const float* __restrict__ Wout,
                            bf16* __restrict__ wqTh, bf16* __restrict__ wqTl,
                            bf16* __restrict__ wkvTh, bf16* __restrict__ wkvTl,
                            bf16* __restrict__ wouth, bf16* __restrict__ woutl,
                            float* __restrict__ biasq, float* __restrict__ biaskv){
    int id = blockIdx.x;
    int tx = threadIdx.x, ty = threadIdx.y;           // (32, 8)
    if (id < 256){
        tss_body(Wq, lnqg, wqTh, wqTl, INNERc, INNERc, id & 15, id >> 4, tx, ty);
    } else if (id < 384){
        int l = id - 256;
        tss_body(Wk, lnkg, wkvTh, wkvTl, DIMc, INNERc, l & 15, l >> 4, tx, ty);
    } else if (id < 512){
        int l = id - 384;
        tss_body(Wv, lnvg, wkvTh + (size_t)INNERc*DIMc, wkvTl + (size_t)INNERc*DIMc,
                 DIMc, INNERc, l & 15, l >> 4, tx, ty);
    } else if (id < 1024){
        int i = (id - 512) * 256 + ty * 32 + tx;
        bf16 h, l; bsplit(Wout[i], h, l);
        wouth[i] = h; woutl[i] = l;
    } else if (id < 1088){
        int n = (id - 1024) * 8 + ty;
        fold_body(Wq, lnqb, nullptr, biasq, INNERc, INNERc, n, tx);
    } else if (id < 1152){
        int n = (id - 1088) * 8 + ty;
        fold_body(Wk, lnkb, bk, biaskv, DIMc, INNERc, n, tx);
    } else {
        int n = (id - 1152) * 8 + ty;
        fold_body(Wv, lnvb, bv, biaskv + INNERc, DIMc, INNERc, n, tx);
    }
}

// ================= merged warp-per-row LayerNorm (lnq + lnkv) =================
__global__ void ln_all_kernel(const float* __restrict__ x, const float* __restrict__ px,
                              bf16* __restrict__ qoh, bf16* __restrict__ qol,
                              bf16* __restrict__ nh, bf16* __restrict__ nl){
    int gw = (blockIdx.x * blockDim.x + threadIdx.x) >> 5;
    int lane = threadIdx.x & 31;
    if (gw < MQ){
        size_t base = (size_t)gw * DIMc + lane * 8;
        float4 a0 = *(const float4*)(x  + base);
        float4 a1 = *(const float4*)(x  + base + 4);
        float4 b0 = *(const float4*)(px + base);
        float4 b1 = *(const float4*)(px + base + 4);
        float va[8] = {a0.x,a0.y,a0.z,a0.w,a1.x,a1.y,a1.z,a1.w};
        float vb[8] = {b0.x,b0.y,b0.z,b0.w,b1.x,b1.y,b1.z,b1.w};
        float s = 0.f, ss = 0.f;
        #pragma unroll
        for (int i = 0; i < 8; i++){ s += va[i] + vb[i]; ss += va[i]*va[i] + vb[i]*vb[i]; }
        #pragma unroll
        for (int o = 16; o > 0; o >>= 1){
            s  += __shfl_xor_sync(0xffffffffu, s, o);
            ss += __shfl_xor_sync(0xffffffffu, ss, o);
        }
        float mean = s * (1.0f/512.0f);
        float var  = ss * (1.0f/512.0f) - mean*mean;
        float rstd = rsqrtf(var + 1e-5f);
        uint32_t ph[4], pl[4];
        #pragma unroll
        for (int i = 0; i < 4; i++){
            bf16 h0,l0,h1,l1;
            bsplit((va[2*i]   - mean)*rstd, h0, l0);
            bsplit((va[2*i+1] - mean)*rstd, h1, l1);
            ph[i] = (uint32_t)__bfloat16_as_ushort(h0) | ((uint32_t)__bfloat16_as_ushort(h1) << 16);
            pl[i] = (uint32_t)__bfloat16_as_ushort(l0) | ((uint32_t)__bfloat16_as_ushort(l1) << 16);
        }
        size_t ob = (size_t)gw * INNERc + lane * 8;
        *(uint4*)(qoh + ob) = make_uint4(ph[0],ph[1],ph[2],ph[3]);
        *(uint4*)(qol + ob) = make_uint4(pl[0],pl[1],pl[2],pl[3]);
        #pragma unroll
        for (int i = 0; i < 4; i++){
            bf16 h0,l0,h1,l1;
            bsplit((vb[2*i]   - mean)*rstd, h0, l0);
            bsplit((vb[2*i+1] - mean)*rstd, h1, l1);
            ph[i] = (uint32_t)__bfloat16_as_ushort(h0) | ((uint32_t)__bfloat16_as_ushort(h1) << 16);
            pl[i] = (uint32_t)__bfloat16_as_ushort(l0) | ((uint32_t)__bfloat16_as_ushort(l1) << 16);
        }
        *(uint4*)(qoh + ob + 256) = make_uint4(ph[0],ph[1],ph[2],ph[3]);
        *(uint4*)(qol + ob + 256) = make_uint4(pl[0],pl[1],pl[2],pl[3]);
    } else {
        int row = gw - MQ;
        const float* src = (row < MQ) ? x : px;
        int r2 = (row < MQ) ? row : row - MQ;
        size_t base = (size_t)r2 * DIMc + lane * 8;
        float4 a0 = *(const float4*)(src + base);
        float4 a1 = *(const float4*)(src + base + 4);
        float v[8] = {a0.x,a0.y,a0.z,a0.w,a1.x,a1.y,a1.z,a1.w};
        float s = 0.f, ss = 0.f;
        #pragma unroll
        for (int i = 0; i < 8; i++){ s += v[i]; ss += v[i]*v[i]; }
        #pragma unroll
        for (int o = 16; o > 0; o >>= 1){
            s  += __shfl_xor_sync(0xffffffffu, s, o);
            ss += __shfl_xor_sync(0xffffffffu, ss, o);
        }
        float mean = s * (1.0f/256.0f);
        float var  = ss * (1.0f/256.0f) - mean*mean;
        float rstd = rsqrtf(var + 1e-5f);
        uint32_t ph[4], pl[4];
        #pragma unroll
        for (int i = 0; i < 4; i++){
            bf16 h0,l0,h1,l1;
            bsplit((v[2*i]   - mean)*rstd, h0, l0);
            bsplit((v[2*i+1] - mean)*rstd, h1, l1);
            ph[i] = (uint32_t)__bfloat16_as_ushort(h0) | ((uint32_t)__bfloat16_as_ushort(h1) << 16);
            pl[i] = (uint32_t)__bfloat16_as_ushort(l0) | ((uint32_t)__bfloat16_as_ushort(l1) << 16);
        }
        size_t ob = (size_t)row * DIMc + lane * 8;
        *(uint4*)(nh + ob) = make_uint4(ph[0],ph[1],ph[2],ph[3]);
        *(uint4*)(nl + ob) = make_uint4(pl[0],pl[1],pl[2],pl[3]);
    }
}

// ============ offsets projection (fp32) — writes transposed (B,H,P,N) ============
__global__ void off_kernel(const float* __restrict__ q, const float* __restrict__ Woff,
                           const float* __restrict__ boff, float* __restrict__ off_out) {
    __shared__ float w[16][INNERc];
    int tid = threadIdx.x;
    for (int i = tid; i < 16 * INNERc; i += 128) w[i >> 9][i & 511] = Woff[i];
    __syncthreads();
    int m = blockIdx.x * 128 + tid;        // b*N + n
    const float* qr = q + (size_t)m * INNERc;
    float acc[16];
    #pragma unroll
    for (int j = 0; j < 16; j++) acc[j] = boff[j];
    for (int k0 = 0; k0 < INNERc; k0 += 4){
        float4 qv = *(const float4*)(qr + k0);
        #pragma unroll
        for (int j = 0; j < 16; j++)
            acc[j] += qv.x * w[j][k0] + qv.y * w[j][k0+1] + qv.z * w[j][k0+2] + qv.w * w[j][k0+3];
    }
    int b = m >> 12, n = m & 4095;
    #pragma unroll
    for (int j = 0; j < 16; j++)
        off_out[((size_t)(b * 16 + j)) * Nn + n] = acc[j];
}

// ================= attention (fused KV layout [row,1024]; hoisted V loads) ======
__global__ void attn_kernel(const float* __restrict__ q, const float* __restrict__ kv,
                            const float* __restrict__ off_t,
                            bf16* __restrict__ aoh, bf16* __restrict__ aol) {
    int gw = (blockIdx.x * blockDim.x + threadIdx.x) >> 5;
    int lane = threadIdx.x & 31;
    if (gw >= MQ * Hh) return;
    int bn = gw / Hh;
    int h  = gw - bn * Hh;
    int b  = bn / Nn;
    int n  = bn - b * Nn;

    float o0 = off_t[((size_t)(b * 16 + h * Pp + 0)) * Nn + n];
    float o1 = off_t[((size_t)(b * 16 + h * Pp + 1)) * Nn + n];
    float t0 = fminf(fmaxf((float)n + o0, 0.f), (float)(2 * Nn - 1));
    float t1 = fminf(fmaxf((float)n + o1, 0.f), (float)(2 * Nn - 1));
    int j0 = (int)t0, j1 = (int)t1;
    int s0 = (j0 >= Nn) ? 1 : 0; int np0 = j0 - s0 * Nn;
    int s1 = (j1 >= Nn) ? 1 : 0; int np1 = j1 - s1 * Nn;

    const float* qb  = q + (size_t)bn * INNERc + h * DHd;
    const float* r0p = kv + ((size_t)(s0 * Bsz + b) * Nn + np0) * (2*INNERc) + h * DHd;
    const float* r1p = kv + ((size_t)(s1 * Bsz + b) * Nn + np1) * (2*INNERc) + h * DHd;
    const float* v0p = r0p + INNERc;
    const float* v1p = r1p + INNERc;

    // issue all gather loads up-front (8 warp-wide loads in flight)
    float qa  = qb[lane],        qc  = qb[lane + 32];
    float k0a = r0p[lane],       k0b = r0p[lane + 32];
    float k1a = r1p[lane],       k1b = r1p[lane + 32];
    float v0a = v0p[lane],       v0b = v0p[lane + 32];
    float v1a = v1p[lane],       v1b = v1p[lane + 32];

    float d0 = qa * k0a + qc * k0b;
    float d1 = qa * k1a + qc * k1b;
    #pragma unroll
    for (int o = 16; o > 0; o >>= 1) {
        d0 += __shfl_xor_sync(0xffffffffu, d0, o);
        d1 += __shfl_xor_sync(0xffffffffu, d1, o);
    }
    const float scale = 0.125f;
    d0 *= scale; d1 *= scale;
    float mx = fmaxf(d0, d1);
    float e0 = __expf(d0 - mx), e1 = __expf(d1 - mx);
    float inv = 1.0f / (e0 + e1);
    float a0 = e0 * inv, a1 = e1 * inv;

    float r0 = a0 * v0a + a1 * v1a;
    float r1 = a0 * v0b + a1 * v1b;
    bf16 hh, ll;
    size_t o_base = (size_t)bn * INNERc + h * DHd;
    bsplit(r0, hh, ll); aoh[o_base + lane]      = hh; aol[o_base + lane]      = ll;
    bsplit(r1, hh, ll); aoh[o_base + lane + 32] = hh; aol[o_base + lane + 32] = ll;
}

// ================= launch =================
extern "C" void kernel_launch(void* const* d_in, const int* in_sizes, int n_in,
                              void* d_out, int out_size) {
    const float* x     = (const float*)d_in[0];
    const float* px    = (const float*)d_in[1];
    const float* lnqg  = (const float*)d_in[2];
    const float* lnqb  = (const float*)d_in[3];
    const float* lnkg  = (const float*)d_in[4];
    const float* lnkb  = (const float*)d_in[5];
    const float* lnvg  = (const float*)d_in[6];
    const float* lnvb  = (const float*)d_in[7];
    const float* Wq    = (const float*)d_in[8];
    const float* Wk    = (const float*)d_in[9];
    const float* bk    = (const float*)d_in[10];
    const float* Wv    = (const float*)d_in[11];
    const float* bv    = (const float*)d_in[12];
    const float* Woff  = (const float*)d_in[13];
    const float* boff  = (const float*)d_in[14];
    const float* Wout  = (const float*)d_in[15];
    const float* bout  = (const float*)d_in[16];

    bf16 *qlnh,*qlnl,*nh,*nl,*aoh,*aol;
    bf16 *wqTh,*wqTl,*wkvTh,*wkvTl,*wouth,*woutl;
    float *qb,*kvb,*biasq,*biaskv;
    cudaGetSymbolAddress((void**)&qlnh, g_qlnh);
    cudaGetSymbolAddress((void**)&qlnl, g_qlnl);
    cudaGetSymbolAddress((void**)&qb,   g_q);
    cudaGetSymbolAddress((void**)&nh,   g_nh);
    cudaGetSymbolAddress((void**)&nl,   g_nl);
    cudaGetSymbolAddress((void**)&kvb,  g_kv);
    cudaGetSymbolAddress((void**)&aoh,  g_aoh);
    cudaGetSymbolAddress((void**)&aol,  g_aol);
    cudaGetSymbolAddress((void**)&wqTh, g_wqTh);
    cudaGetSymbolAddress((void**)&wqTl, g_wqTl);
    cudaGetSymbolAddress((void**)&wkvTh, g_wkvTh);
    cudaGetSymbolAddress((void**)&wkvTl, g_wkvTl);
    cudaGetSymbolAddress((void**)&wouth, g_wouth);
    cudaGetSymbolAddress((void**)&woutl, g_woutl);
    cudaGetSymbolAddress((void**)&biasq,  g_biasq);
    cudaGetSymbolAddress((void**)&biaskv, g_biaskv);

    cudaFuncSetAttribute((const void*)bf16x3_gemm<1,128>, cudaFuncAttributeMaxDynamicSharedMemorySize, GEMM_SMEM_128);
    cudaFuncSetAttribute((const void*)bf16x3_gemm<1,64>,  cudaFuncAttributeMaxDynamicSharedMemorySize, GEMM_SMEM_64);

    float* out_main = (float*)d_out;
    float* out_off  = out_main + (size_t)MQ * DIMc;

    // 0: all weight prep
    prep_kernel<<<1216, dim3(32,8)>>>(Wq, lnqg, lnqb, Wk, lnkg, lnkb, bk,
                                      Wv, lnvg, lnvb, bv, Wout,
                                      wqTh, wqTl, wkvTh, wkvTl, wouth, woutl,
                                      biasq, biaskv);
    // 1: merged LN (warp per row)
    ln_all_kernel<<<(MQ + MKV)/8, 256>>>(x, px, qlnh, qlnl, nh, nl);

    // 2: kv = nrm @ [foldedWk | foldedWv] + biaskv
    bf16x3_gemm<1,128><<<dim3(2*INNERc/128, MKV/128), 256, GEMM_SMEM_128>>>(nh, nl, wkvTh, wkvTl, biaskv, kvb, 2*INNERc, DIMc);
    // 3: q = nrm_q @ foldedWq + biasq
    bf16x3_gemm<1,128><<<dim3(INNERc/128, MQ/128),  256, GEMM_SMEM_128>>>(qlnh, qlnl, wqTh, wqTl, biasq, qb, INNERc, INNERc);

    // 4,5: offsets + attention
    off_kernel<<<MQ/128, 128>>>(qb, Woff, boff, out_off);
    attn_kernel<<<(MQ*Hh)/8, 256>>>(qb, kvb, out_off, aoh, aol);

    // 6: out = ao @ Wout^T + bout  (NT=64 -> 512 blocks, fills the chip)
    bf16x3_gemm<1,64><<<dim3(DIMc/64, MQ/128), 256, GEMM_SMEM_64>>>(aoh, aol, wouth, woutl, bout, out_main, DIMc, INNERc);
}

// round 13
// speedup vs baseline: 1.4897x; 1.0809x over previous
#include <cuda_runtime.h>
#include <cuda_bf16.h>
#include <cstdint>
#include <math.h>

#define Bsz 4
#define Nn 4096
#define DIMc 256
#define Hh 8
#define DHd 64
#define Pp 2
#define INNERc 512
#define MQ (Bsz*Nn)      /* 16384 */
#define MKV (2*Bsz*Nn)   /* 32768 */

typedef __nv_bfloat16 bf16;

// ---------------- scratch (device globals) ----------------
__device__ bf16  g_qlnh[MQ * INNERc];
__device__ bf16  g_qlnl[MQ * INNERc];
__device__ float g_q   [MQ * INNERc];
__device__ bf16  g_nh  [MKV * DIMc];
__device__ bf16  g_nl  [MKV * DIMc];
__device__ float g_kv  [MKV * 2 * INNERc];
__device__ bf16  g_aoh [MQ * INNERc];
__device__ bf16  g_aol [MQ * INNERc];
__device__ bf16  g_wqTh[INNERc * INNERc];
__device__ bf16  g_wqTl[INNERc * INNERc];
__device__ bf16  g_wkvTh[2 * INNERc * DIMc];
__device__ bf16  g_wkvTl[2 * INNERc * DIMc];
__device__ bf16  g_wouth[DIMc * INNERc];
__device__ bf16  g_woutl[DIMc * INNERc];
__device__ float g_biasq [INNERc];
__device__ float g_biaskv[2 * INNERc];

// ================= helpers =================
__device__ __forceinline__ uint32_t smem_u32(const void* p){
    uint32_t a;
    asm("{ .reg .u64 t; cvta.to.shared.u64 t, %1; cvt.u32.u64 %0, t; }" : "=r"(a) : "l"(p));
    return a;
}
__device__ __forceinline__ void bsplit(float v, bf16& h, bf16& l){
    h = __float2bfloat16(v);
    l = __float2bfloat16(v - __bfloat162float(h));
}
__device__ __forceinline__ void mma_bf16(float d[4], const uint32_t a[4], const uint32_t b[2]){
    asm volatile("mma.sync.aligned.m16n8k16.row.col.f32.bf16.bf16.f32 "
        "{%0,%1,%2,%3}, {%4,%5,%6,%7}, {%8,%9}, {%0,%1,%2,%3};"
        : "+f"(d[0]),"+f"(d[1]),"+f"(d[2]),"+f"(d[3])
        : "r"(a[0]),"r"(a[1]),"r"(a[2]),"r"(a[3]),"r"(b[0]),"r"(b[1]));
}
__device__ __forceinline__ void ldsm4(uint32_t r[4], uint32_t addr){
    asm volatile("ldmatrix.sync.aligned.m8n8.x4.shared.b16 {%0,%1,%2,%3}, [%4];"
        : "=r"(r[0]),"=r"(r[1]),"=r"(r[2]),"=r"(r[3]) : "r"(addr));
}
__device__ __forceinline__ void cp16(uint32_t dst, const void* src){
    asm volatile("cp.async.cg.shared.global [%0], [%1], 16;" :: "r"(dst), "l"(src));
}
// swizzled byte offset within a plane: row has 64B = 4 x 16B slots
__device__ __forceinline__ uint32_t swz(int r, int s){
    return (uint32_t)(r * 64 + ((s ^ ((r >> 1) & 3)) << 4));
}

// ================= bf16x3 tensor-core GEMM =================
// C[M,Ntot] = (Ah+Al)[M,K] @ (Bh+Bl)[Ntot,K]^T (+bias), x3 terms.
// 256 thr, tile 128xNT, K-chunk 32, 3-stage cp.async (depth 2),
// swizzled 64B rows, 2 CTAs/SM, one barrier per chunk, load-after-compute.
#define TILE_A 8192

template<int HAS_BIAS, int NT>
__global__ void __launch_bounds__(256, 2)
bf16x3_gemm(const bf16* __restrict__ Ah, const bf16* __restrict__ Al,
            const bf16* __restrict__ Bh, const bf16* __restrict__ Bl,
            const float* __restrict__ bias, float* __restrict__ C,
            int Ntot, int K)
{
    constexpr int NJ  = NT / 32;
    constexpr int NJP = NT / 64;
    constexpr int TILE_BP = NT * 64;
    constexpr int STAGE = 2*TILE_A + 2*TILE_BP;

    extern __shared__ char smem[];
    const uint32_t sb = smem_u32(smem);
    const int tid = threadIdx.x, lane = tid & 31, wid = tid >> 5;
    const int wm = wid >> 2, wn = wid & 3;
    const int bm = blockIdx.y * 128, bn = blockIdx.x * NT;
    const int NC = K >> 5;

    const int lr  = tid >> 2;
    const int lcc = tid & 3;
    const uint32_t w0 = swz(lr, lcc), w1 = swz(lr + 64, lcc);

    uint32_t aoff[2][4], boff[2][NJP];
    #pragma unroll
    for (int ks = 0; ks < 2; ks++){
        const int slot = (lane >> 4) + ks * 2;
        #pragma unroll
        for (int i = 0; i < 4; i++)
            aoff[ks][i] = swz(wm*64 + i*16 + (lane & 15), slot);
        #pragma unroll
        for (int jp = 0; jp < NJP; jp++)
            boff[ks][jp] = 2*TILE_A + swz(wn*(NT/4) + jp*16 + (lane & 15), slot);
    }

    auto load_stage = [&](int buf, int kc){
        uint32_t base = sb + buf * STAGE;
        size_t ao = (size_t)(bm + lr) * K + kc + lcc * 8;
        size_t bo = (size_t)(bn + lr) * K + kc + lcc * 8;
        size_t row64 = (size_t)64 * K;
        cp16(base + w0,           Ah + ao);
        cp16(base + w1,           Ah + ao + row64);
        cp16(base + TILE_A + w0,  Al + ao);
        cp16(base + TILE_A + w1,  Al + ao + row64);
        cp16(base + 2*TILE_A + w0,            Bh + bo);
        cp16(base + 2*TILE_A + TILE_BP + w0,  Bl + bo);
        if (NT == 128){
            cp16(base + 2*TILE_A + w1,           Bh + bo + row64);
            cp16(base + 2*TILE_A + TILE_BP + w1, Bl + bo + row64);
        }
        asm volatile("cp.async.commit_group;" ::: "memory");
    };

    float acc[4][NJ][4] = {};

    auto compute = [&](int buf){
        uint32_t base = sb + buf * STAGE;
        #pragma unroll
        for (int ks = 0; ks < 2; ks++){
            uint32_t BH[NJ][2], BL[NJ][2];
            #pragma unroll
            for (int jp = 0; jp < NJP; jp++){
                uint32_t a = base + boff[ks][jp];
                uint32_t r4[4];
                ldsm4(r4, a);
                BH[jp*2][0]=r4[0]; BH[jp*2+1][0]=r4[1]; BH[jp*2][1]=r4[2]; BH[jp*2+1][1]=r4[3];
                ldsm4(r4, a + TILE_BP);
                BL[jp*2][0]=r4[0]; BL[jp*2+1][0]=r4[1]; BL[jp*2][1]=r4[2]; BL[jp*2+1][1]=r4[3];
            }
            #pragma unroll
            for (int i = 0; i < 4; i++){
                uint32_t a = base + aoff[ks][i];
                uint32_t ah[4], al_[4];
                ldsm4(ah,  a);
                ldsm4(al_, a + TILE_A);
                #pragma unroll
                for (int j = 0; j < NJ; j++) mma_bf16(acc[i][j], ah,  BH[j]);
                #pragma unroll
                for (int j = 0; j < NJ; j++) mma_bf16(acc[i][j], ah,  BL[j]);
                #pragma unroll
                for (int j = 0; j < NJ; j++) mma_bf16(acc[i][j], al_, BH[j]);
            }
        }
    };

    load_stage(0, 0);
    load_stage(1, 32);

    for (int c = 0; c < NC; c++){
        if (c < NC - 1) asm volatile("cp.async.wait_group 1;" ::: "memory");
        else            asm volatile("cp.async.wait_group 0;" ::: "memory");
        __syncthreads();
        compute(c % 3);
        if (c + 2 < NC) load_stage((c + 2) % 3, (c + 2) * 32);
    }

    #pragma unroll
    for (int i = 0; i < 4; i++){
        int r0 = bm + wm*64 + i*16 + (lane >> 2);
        #pragma unroll
        for (int j = 0; j < NJ; j++){
            int c0 = bn + wn*(NT/4) + j*8 + (lane & 3)*2;
            float b0 = 0.f, b1 = 0.f;
            if (HAS_BIAS){ b0 = bias[c0]; b1 = bias[c0+1]; }
            *(float2*)(C + (size_t)r0 * Ntot + c0)     = make_float2(acc[i][j][0]+b0, acc[i][j][1]+b1);
            *(float2*)(C + (size_t)(r0+8) * Ntot + c0) = make_float2(acc[i][j][2]+b0, acc[i][j][3]+b1);
        }
    }
}

#define GEMM_SMEM_128 (3*(2*TILE_A + 2*128*64))
#define GEMM_SMEM_64  (3*(2*TILE_A + 2*64*64))

// ================= merged weight prep (single launch) =================
__device__ __forceinline__ void tss_body(const float* in, const float* g,
                                         bf16* oh, bf16* ol, int R, int C,
                                         int bx, int by, int tx, int ty){
    __shared__ float tile[32][33];
    int c0 = bx * 32, r0 = by * 32;
    #pragma unroll
    for (int i = 0; i < 32; i += 8){
        int r = r0 + ty + i;
        tile[ty + i][tx] = in[(size_t)r * C + c0 + tx] * g[r];
    }
    __syncthreads();
    #pragma unroll
    for (int i = 0; i < 32; i += 8){
        float v = tile[tx][ty + i];
        bf16 h, l; bsplit(v, h, l);
        size_t o = (size_t)(c0 + ty + i) * R + r0 + tx;
        oh[o] = h; ol[o] = l;
    }
}
__device__ __forceinline__ void fold_body(const float* W, const float* beta,
                                          const float* base, float* out,
                                          int K, int N, int n, int lane){
    float s = 0.f;
    for (int k = lane; k < K; k += 32) s += beta[k] * W[(size_t)k * N + n];
    #pragma unroll
    for (int o = 16; o > 0; o >>= 1) s += __shfl_xor_sync(0xffffffffu, s, o);
    if (lane == 0) out[n] = s + (base ? base[n] : 0.f);
}

__global__ void prep_kernel(const float* __restrict__ Wq, const float* __restrict__ lnqg, const float* __restrict__ lnqb,
                            const float* __restrict__ Wk, const float* __restrict__ lnkg, const float* __restrict__ lnkb, const float* __restrict__ bk,
                            const float* __restrict__ Wv, const float* __restrict__ lnvg, const float* __restrict__ lnvb, const float* __restrict__ bv,
                            const float* __restrict__ Wout,
                            bf16* __restrict__ wqTh, bf16* __restrict__ wqTl,
                            bf16* __restrict__ wkvTh, bf16* __restrict__ wkvTl,
                            bf16* __restrict__ wouth, bf16* __restrict__ woutl,
                            float* __restrict__ biasq, float* __restrict__ biaskv){
    int id = blockIdx.x;
    int tx = threadIdx.x, ty = threadIdx.y;           // (32, 8)
    if (id < 256){
        tss_body(Wq, lnqg, wqTh, wqTl, INNERc, INNERc, id & 15, id >> 4, tx, ty);
    } else if (id < 384){
        int l = id - 256;
        tss_body(Wk, lnkg, wkvTh, wkvTl, DIMc, INNERc, l & 15, l >> 4, tx, ty);
    } else if (id < 512){
        int l = id - 384;
        tss_body(Wv, lnvg, wkvTh + (size_t)INNERc*DIMc, wkvTl + (size_t)INNERc*DIMc,
                 DIMc, INNERc, l & 15, l >> 4, tx, ty);
    } else if (id < 1024){
        int i = (id - 512) * 256 + ty * 32 + tx;
        bf16 h, l; bsplit(Wout[i], h, l);
        wouth[i] = h; woutl[i] = l;
    } else if (id < 1088){
        int n = (id - 1024) * 8 + ty;
        fold_body(Wq, lnqb, nullptr, biasq, INNERc, INNERc, n, tx);
    } else if (id < 1152){
        int n = (id - 1088) * 8 + ty;
        fold_body(Wk, lnkb, bk, biaskv, DIMc, INNERc, n, tx);
    } else {
        int n = (id - 1152) * 8 + ty;
        fold_body(Wv, lnvb, bv, biaskv + INNERc, DIMc, INNERc, n, tx);
    }
}

// ================= merged warp-per-row LayerNorm (lnq + lnkv) =================
__global__ void ln_all_kernel(const float* __restrict__ x, const float* __restrict__ px,
                              bf16* __restrict__ qoh, bf16* __restrict__ qol,
                              bf16* __restrict__ nh, bf16* __restrict__ nl){
    int gw = (blockIdx.x * blockDim.x + threadIdx.x) >> 5;
    int lane = threadIdx.x & 31;
    if (gw < MQ){
        size_t base = (size_t)gw * DIMc + lane * 8;
        float4 a0 = *(const float4*)(x  + base);
        float4 a1 = *(const float4*)(x  + base + 4);
        float4 b0 = *(const float4*)(px + base);
        float4 b1 = *(const float4*)(px + base + 4);
        float va[8] = {a0.x,a0.y,a0.z,a0.w,a1.x,a1.y,a1.z,a1.w};
        float vb[8] = {b0.x,b0.y,b0.z,b0.w,b1.x,b1.y,b1.z,b1.w};
        float s = 0.f, ss = 0.f;
        #pragma unroll
        for (int i = 0; i < 8; i++){ s += va[i] + vb[i]; ss += va[i]*va[i] + vb[i]*vb[i]; }
        #pragma unroll
        for (int o = 16; o > 0; o >>= 1){
            s  += __shfl_xor_sync(0xffffffffu, s, o);
            ss += __shfl_xor_sync(0xffffffffu, ss, o);
        }
        float mean = s * (1.0f/512.0f);
        float var  = ss * (1.0f/512.0f) - mean*mean;
        float rstd = rsqrtf(var + 1e-5f);
        uint32_t ph[4], pl[4];
        #pragma unroll
        for (int i = 0; i < 4; i++){
            bf16 h0,l0,h1,l1;
            bsplit((va[2*i]   - mean)*rstd, h0, l0);
            bsplit((va[2*i+1] - mean)*rstd, h1, l1);
            ph[i] = (uint32_t)__bfloat16_as_ushort(h0) | ((uint32_t)__bfloat16_as_ushort(h1) << 16);
            pl[i] = (uint32_t)__bfloat16_as_ushort(l0) | ((uint32_t)__bfloat16_as_ushort(l1) << 16);
        }
        size_t ob = (size_t)gw * INNERc + lane * 8;
        *(uint4*)(qoh + ob) = make_uint4(ph[0],ph[1],ph[2],ph[3]);
        *(uint4*)(qol + ob) = make_uint4(pl[0],pl[1],pl[2],pl[3]);
        #pragma unroll
        for (int i = 0; i < 4; i++){
            bf16 h0,l0,h1,l1;
            bsplit((vb[2*i]   - mean)*rstd, h0, l0);
            bsplit((vb[2*i+1] - mean)*rstd, h1, l1);
            ph[i] = (uint32_t)__bfloat16_as_ushort(h0) | ((uint32_t)__bfloat16_as_ushort(h1) << 16);
            pl[i] = (uint32_t)__bfloat16_as_ushort(l0) | ((uint32_t)__bfloat16_as_ushort(l1) << 16);
        }
        *(uint4*)(qoh + ob + 256) = make_uint4(ph[0],ph[1],ph[2],ph[3]);
        *(uint4*)(qol + ob + 256) = make_uint4(pl[0],pl[1],pl[2],pl[3]);
    } else {
        int row = gw - MQ;
        const float* src = (row < MQ) ? x : px;
        int r2 = (row < MQ) ? row : row - MQ;
        size_t base = (size_t)r2 * DIMc + lane * 8;
        float4 a0 = *(const float4*)(src + base);
        float4 a1 = *(const float4*)(src + base + 4);
        float v[8] = {a0.x,a0.y,a0.z,a0.w,a1.x,a1.y,a1.z,a1.w};
        float s = 0.f, ss = 0.f;
        #pragma unroll
        for (int i = 0; i < 8; i++){ s += v[i]; ss += v[i]*v[i]; }
        #pragma unroll
        for (int o = 16; o > 0; o >>= 1){
            s  += __shfl_xor_sync(0xffffffffu, s, o);
            ss += __shfl_xor_sync(0xffffffffu, ss, o);
        }
        float mean = s * (1.0f/256.0f);
        float var  = ss * (1.0f/256.0f) - mean*mean;
        float rstd = rsqrtf(var + 1e-5f);
        uint32_t ph[4], pl[4];
        #pragma unroll
        for (int i = 0; i < 4; i++){
            bf16 h0,l0,h1,l1;
            bsplit((v[2*i]   - mean)*rstd, h0, l0);
            bsplit((v[2*i+1] - mean)*rstd, h1, l1);
            ph[i] = (uint32_t)__bfloat16_as_ushort(h0) | ((uint32_t)__bfloat16_as_ushort(h1) << 16);
            pl[i] = (uint32_t)__bfloat16_as_ushort(l0) | ((uint32_t)__bfloat16_as_ushort(l1) << 16);
        }
        size_t ob = (size_t)row * DIMc + lane * 8;
        *(uint4*)(nh + ob) = make_uint4(ph[0],ph[1],ph[2],ph[3]);
        *(uint4*)(nl + ob) = make_uint4(pl[0],pl[1],pl[2],pl[3]);
    }
}

// ============ offsets projection v2: 8 threads/row, interleaved K, coalesced ====
// block 256 = 32 rows x 8 k-slices; grid = MQ/32
__global__ void off_kernel(const float* __restrict__ q, const float* __restrict__ Woff,
                           const float* __restrict__ boff, float* __restrict__ off_out) {
    __shared__ float w[16 * INNERc];
    int tid = threadIdx.x;
    for (int i = tid; i < 16 * INNERc / 4; i += 256)
        ((float4*)w)[i] = ((const float4*)Woff)[i];
    __syncthreads();
    int row = blockIdx.x * 32 + (tid >> 3);   // b*N + n
    int ks  = tid & 7;
    const float* qr = q + (size_t)row * INNERc;
    float acc[16];
    #pragma unroll
    for (int j = 0; j < 16; j++) acc[j] = 0.f;
    #pragma unroll
    for (int m = 0; m < 16; m++){
        int kb = m * 32 + ks * 4;             // interleaved slice -> conflict-free banks
        float4 qv = *(const float4*)(qr + kb);
        #pragma unroll
        for (int j = 0; j < 16; j++){
            const float* wj = w + j * INNERc + kb;
            acc[j] += qv.x*wj[0] + qv.y*wj[1] + qv.z*wj[2] + qv.w*wj[3];
        }
    }
    #pragma unroll
    for (int j = 0; j < 16; j++){
        acc[j] += __shfl_xor_sync(0xffffffffu, acc[j], 1);
        acc[j] += __shfl_xor_sync(0xffffffffu, acc[j], 2);
        acc[j] += __shfl_xor_sync(0xffffffffu, acc[j], 4);
    }
    if (ks == 0){
        int b = row >> 12, n = row & 4095;
        #pragma unroll
        for (int j = 0; j < 16; j++)
            off_out[((size_t)(b * 16 + j)) * Nn + n] = acc[j] + boff[j];
    }
}

// ================= attention (fused KV layout [row,1024]; hoisted loads) ======
__global__ void attn_kernel(const float* __restrict__ q, const float* __restrict__ kv,
                            const float* __restrict__ off_t,
                            bf16* __restrict__ aoh, bf16* __restrict__ aol) {
    int gw = (blockIdx.x * blockDim.x + threadIdx.x) >> 5;
    int lane = threadIdx.x & 31;
    if (gw >= MQ * Hh) return;
    int bn = gw / Hh;
    int h  = gw - bn * Hh;
    int b  = bn / Nn;
    int n  = bn - b * Nn;

    float o0 = off_t[((size_t)(b * 16 + h * Pp + 0)) * Nn + n];
    float o1 = off_t[((size_t)(b * 16 + h * Pp + 1)) * Nn + n];
    float t0 = fminf(fmaxf((float)n + o0, 0.f), (float)(2 * Nn - 1));
    float t1 = fminf(fmaxf((float)n + o1, 0.f), (float)(2 * Nn - 1));
    int j0 = (int)t0, j1 = (int)t1;
    int s0 = (j0 >= Nn) ? 1 : 0; int np0 = j0 - s0 * Nn;
    int s1 = (j1 >= Nn) ? 1 : 0; int np1 = j1 - s1 * Nn;

    const float* qb  = q + (size_t)bn * INNERc + h * DHd;
    const float* r0p = kv + ((size_t)(s0 * Bsz + b) * Nn + np0) * (2*INNERc) + h * DHd;
    const float* r1p = kv + ((size_t)(s1 * Bsz + b) * Nn + np1) * (2*INNERc) + h * DHd;
    const float* v0p = r0p + INNERc;
    const float* v1p = r1p + INNERc;

    float qa  = qb[lane],        qc  = qb[lane + 32];
    float k0a = r0p[lane],       k0b = r0p[lane + 32];
    float k1a = r1p[lane],       k1b = r1p[lane + 32];
    float v0a = v0p[lane],       v0b = v0p[lane + 32];
    float v1a = v1p[lane],       v1b = v1p[lane + 32];

    float d0 = qa * k0a + qc * k0b;
    float d1 = qa * k1a + qc * k1b;
    #pragma unroll
    for (int o = 16; o > 0; o >>= 1) {
        d0 += __shfl_xor_sync(0xffffffffu, d0, o);
        d1 += __shfl_xor_sync(0xffffffffu, d1, o);
    }
    const float scale = 0.125f;
    d0 *= scale; d1 *= scale;
    float mx = fmaxf(d0, d1);
    float e0 = __expf(d0 - mx), e1 = __expf(d1 - mx);
    float inv = 1.0f / (e0 + e1);
    float a0 = e0 * inv, a1 = e1 * inv;

    float r0 = a0 * v0a + a1 * v1a;
    float r1 = a0 * v0b + a1 * v1b;
    bf16 hh, ll;
    size_t o_base = (size_t)bn * INNERc + h * DHd;
    bsplit(r0, hh, ll); aoh[o_base + lane]      = hh; aol[o_base + lane]      = ll;
    bsplit(r1, hh, ll); aoh[o_base + lane + 32] = hh; aol[o_base + lane + 32] = ll;
}

// ================= launch =================
extern "C" void kernel_launch(void* const* d_in, const int* in_sizes, int n_in,
                              void* d_out, int out_size) {
    const float* x     = (const float*)d_in[0];
    const float* px    = (const float*)d_in[1];
    const float* lnqg  = (const float*)d_in[2];
    const float* lnqb  = (const float*)d_in[3];
    const float* lnkg  = (const float*)d_in[4];
    const float* lnkb  = (const float*)d_in[5];
    const float* lnvg  = (const float*)d_in[6];
    const float* lnvb  = (const float*)d_in[7];
    const float* Wq    = (const float*)d_in[8];
    const float* Wk    = (const float*)d_in[9];
    const float* bk    = (const float*)d_in[10];
    const float* Wv    = (const float*)d_in[11];
    const float* bv    = (const float*)d_in[12];
    const float* Woff  = (const float*)d_in[13];
    const float* boff  = (const float*)d_in[14];
    const float* Wout  = (const float*)d_in[15];
    const float* bout  = (const float*)d_in[16];

    bf16 *qlnh,*qlnl,*nh,*nl,*aoh,*aol;
    bf16 *wqTh,*wqTl,*wkvTh,*wkvTl,*wouth,*woutl;
    float *qb,*kvb,*biasq,*biaskv;
    cudaGetSymbolAddress((void**)&qlnh, g_qlnh);
    cudaGetSymbolAddress((void**)&qlnl, g_qlnl);
    cudaGetSymbolAddress((void**)&qb,   g_q);
    cudaGetSymbolAddress((void**)&nh,   g_nh);
    cudaGetSymbolAddress((void**)&nl,   g_nl);
    cudaGetSymbolAddress((void**)&kvb,  g_kv);
    cudaGetSymbolAddress((void**)&aoh,  g_aoh);
    cudaGetSymbolAddress((void**)&aol,  g_aol);
    cudaGetSymbolAddress((void**)&wqTh, g_wqTh);
    cudaGetSymbolAddress((void**)&wqTl, g_wqTl);
    cudaGetSymbolAddress((void**)&wkvTh, g_wkvTh);
    cudaGetSymbolAddress((void**)&wkvTl, g_wkvTl);
    cudaGetSymbolAddress((void**)&wouth, g_wouth);
    cudaGetSymbolAddress((void**)&woutl, g_woutl);
    cudaGetSymbolAddress((void**)&biasq,  g_biasq);
    cudaGetSymbolAddress((void**)&biaskv, g_biaskv);

    cudaFuncSetAttribute((const void*)bf16x3_gemm<1,128>, cudaFuncAttributeMaxDynamicSharedMemorySize, GEMM_SMEM_128);
    cudaFuncSetAttribute((const void*)bf16x3_gemm<1,64>,  cudaFuncAttributeMaxDynamicSharedMemorySize, GEMM_SMEM_64);

    float* out_main = (float*)d_out;
    float* out_off  = out_main + (size_t)MQ * DIMc;

    // 0: all weight prep
    prep_kernel<<<1216, dim3(32,8)>>>(Wq, lnqg, lnqb, Wk, lnkg, lnkb, bk,
                                      Wv, lnvg, lnvb, bv, Wout,
                                      wqTh, wqTl, wkvTh, wkvTl, wouth, woutl,
                                      biasq, biaskv);
    // 1: merged LN (warp per row)
    ln_all_kernel<<<(MQ + MKV)/8, 256>>>(x, px, qlnh, qlnl, nh, nl);

    // 2: kv = nrm @ [foldedWk | foldedWv] + biaskv
    bf16x3_gemm<1,128><<<dim3(2*INNERc/128, MKV/128), 256, GEMM_SMEM_128>>>(nh, nl, wkvTh, wkvTl, biaskv, kvb, 2*INNERc, DIMc);
    // 3: q = nrm_q @ foldedWq + biasq
    bf16x3_gemm<1,128><<<dim3(INNERc/128, MQ/128),  256, GEMM_SMEM_128>>>(qlnh, qlnl, wqTh, wqTl, biasq, qb, INNERc, INNERc);

    // 4,5: offsets + attention
    off_kernel<<<MQ/32, 256>>>(qb, Woff, boff, out_off);
    attn_kernel<<<(MQ*Hh)/8, 256>>>(qb, kvb, out_off, aoh, aol);

    // 6: out = ao @ Wout^T + bout
    bf16x3_gemm<1,64><<<dim3(DIMc/64, MQ/128), 256, GEMM_SMEM_64>>>(aoh, aol, wouth, woutl, bout, out_main, DIMc, INNERc);
}

// round 14
// speedup vs baseline: 1.5001x; 1.0070x over previous
#include <cuda_runtime.h>
#include <cuda_bf16.h>
#include <cstdint>
#include <math.h>

#define Bsz 4
#define Nn 4096
#define DIMc 256
#define Hh 8
#define DHd 64
#define Pp 2
#define INNERc 512
#define MQ (Bsz*Nn)      /* 16384 */
#define MKV (2*Bsz*Nn)   /* 32768 */

typedef __nv_bfloat16 bf16;

// ---------------- scratch (device globals) ----------------
__device__ bf16  g_qlnh[MQ * INNERc];
__device__ bf16  g_qlnl[MQ * INNERc];
__device__ float g_q   [MQ * INNERc];
__device__ bf16  g_nh  [MKV * DIMc];
__device__ bf16  g_nl  [MKV * DIMc];
__device__ float g_kv  [MKV * 2 * INNERc];
__device__ bf16  g_aoh [MQ * INNERc];
__device__ bf16  g_aol [MQ * INNERc];
__device__ bf16  g_wqTh[INNERc * INNERc];
__device__ bf16  g_wqTl[INNERc * INNERc];
__device__ bf16  g_wkvTh[2 * INNERc * DIMc];
__device__ bf16  g_wkvTl[2 * INNERc * DIMc];
__device__ bf16  g_wouth[DIMc * INNERc];
__device__ bf16  g_woutl[DIMc * INNERc];
__device__ float g_biasq [INNERc];
__device__ float g_biaskv[2 * INNERc];

// ================= helpers =================
__device__ __forceinline__ uint32_t smem_u32(const void* p){
    uint32_t a;
    asm("{ .reg .u64 t; cvta.to.shared.u64 t, %1; cvt.u32.u64 %0, t; }" : "=r"(a) : "l"(p));
    return a;
}
__device__ __forceinline__ void bsplit(float v, bf16& h, bf16& l){
    h = __float2bfloat16(v);
    l = __float2bfloat16(v - __bfloat162float(h));
}
__device__ __forceinline__ void mma_bf16(float d[4], const uint32_t a[4], const uint32_t b[2]){
    asm volatile("mma.sync.aligned.m16n8k16.row.col.f32.bf16.bf16.f32 "
        "{%0,%1,%2,%3}, {%4,%5,%6,%7}, {%8,%9}, {%0,%1,%2,%3};"
        : "+f"(d[0]),"+f"(d[1]),"+f"(d[2]),"+f"(d[3])
        : "r"(a[0]),"r"(a[1]),"r"(a[2]),"r"(a[3]),"r"(b[0]),"r"(b[1]));
}
__device__ __forceinline__ void ldsm4(uint32_t r[4], uint32_t addr){
    asm volatile("ldmatrix.sync.aligned.m8n8.x4.shared.b16 {%0,%1,%2,%3}, [%4];"
        : "=r"(r[0]),"=r"(r[1]),"=r"(r[2]),"=r"(r[3]) : "r"(addr));
}
__device__ __forceinline__ void cp16(uint32_t dst, const void* src){
    asm volatile("cp.async.cg.shared.global [%0], [%1], 16;" :: "r"(dst), "l"(src));
}
// swizzled byte offset within a plane: row has 64B = 4 x 16B slots
__device__ __forceinline__ uint32_t swz(int r, int s){
    return (uint32_t)(r * 64 + ((s ^ ((r >> 1) & 3)) << 4));
}

// ================= bf16x3 tensor-core GEMM =================
// C[M,Ntot] = (Ah+Al)[M,K] @ (Bh+Bl)[Ntot,K]^T (+bias), x3 terms.
// 256 thr, tile 128xNT, K-chunk 32, 3-stage cp.async (depth 2),
// swizzled 64B rows, 2 CTAs/SM, one barrier per chunk, load-after-compute,
// hoisted global pointers.
#define TILE_A 8192

template<int HAS_BIAS, int NT>
__global__ void __launch_bounds__(256, 2)
bf16x3_gemm(const bf16* __restrict__ Ah, const bf16* __restrict__ Al,
            const bf16* __restrict__ Bh, const bf16* __restrict__ Bl,
            const float* __restrict__ bias, float* __restrict__ C,
            int Ntot, int K)
{
    constexpr int NJ  = NT / 32;
    constexpr int NJP = NT / 64;
    constexpr int TILE_BP = NT * 64;
    constexpr int STAGE = 2*TILE_A + 2*TILE_BP;

    extern __shared__ char smem[];
    const uint32_t sb = smem_u32(smem);
    const int tid = threadIdx.x, lane = tid & 31, wid = tid >> 5;
    const int wm = wid >> 2, wn = wid & 3;
    const int bm = blockIdx.y * 128, bn = blockIdx.x * NT;
    const int NC = K >> 5;

    const int lr  = tid >> 2;
    const int lcc = tid & 3;
    const uint32_t w0 = swz(lr, lcc), w1 = swz(lr + 64, lcc);

    // hoisted global source pointers
    const size_t row64 = (size_t)64 * K;
    const bf16* pAh = Ah + (size_t)(bm + lr) * K + lcc * 8;
    const bf16* pAl = Al + (size_t)(bm + lr) * K + lcc * 8;
    const bf16* pBh = Bh + (size_t)(bn + lr) * K + lcc * 8;
    const bf16* pBl = Bl + (size_t)(bn + lr) * K + lcc * 8;

    uint32_t aoff[2][4], boff[2][NJP];
    #pragma unroll
    for (int ks = 0; ks < 2; ks++){
        const int slot = (lane >> 4) + ks * 2;
        #pragma unroll
        for (int i = 0; i < 4; i++)
            aoff[ks][i] = swz(wm*64 + i*16 + (lane & 15), slot);
        #pragma unroll
        for (int jp = 0; jp < NJP; jp++)
            boff[ks][jp] = 2*TILE_A + swz(wn*(NT/4) + jp*16 + (lane & 15), slot);
    }

    auto load_stage = [&](int buf, int kc){
        uint32_t base = sb + buf * STAGE;
        cp16(base + w0,           pAh + kc);
        cp16(base + w1,           pAh + kc + row64);
        cp16(base + TILE_A + w0,  pAl + kc);
        cp16(base + TILE_A + w1,  pAl + kc + row64);
        cp16(base + 2*TILE_A + w0,            pBh + kc);
        cp16(base + 2*TILE_A + TILE_BP + w0,  pBl + kc);
        if (NT == 128){
            cp16(base + 2*TILE_A + w1,           pBh + kc + row64);
            cp16(base + 2*TILE_A + TILE_BP + w1, pBl + kc + row64);
        }
        asm volatile("cp.async.commit_group;" ::: "memory");
    };

    float acc[4][NJ][4] = {};

    auto compute = [&](int buf){
        uint32_t base = sb + buf * STAGE;
        #pragma unroll
        for (int ks = 0; ks < 2; ks++){
            uint32_t BH[NJ][2], BL[NJ][2];
            #pragma unroll
            for (int jp = 0; jp < NJP; jp++){
                uint32_t a = base + boff[ks][jp];
                uint32_t r4[4];
                ldsm4(r4, a);
                BH[jp*2][0]=r4[0]; BH[jp*2+1][0]=r4[1]; BH[jp*2][1]=r4[2]; BH[jp*2+1][1]=r4[3];
                ldsm4(r4, a + TILE_BP);
                BL[jp*2][0]=r4[0]; BL[jp*2+1][0]=r4[1]; BL[jp*2][1]=r4[2]; BL[jp*2+1][1]=r4[3];
            }
            #pragma unroll
            for (int i = 0; i < 4; i++){
                uint32_t a = base + aoff[ks][i];
                uint32_t ah[4], al_[4];
                ldsm4(ah,  a);
                ldsm4(al_, a + TILE_A);
                #pragma unroll
                for (int j = 0; j < NJ; j++) mma_bf16(acc[i][j], ah,  BH[j]);
                #pragma unroll
                for (int j = 0; j < NJ; j++) mma_bf16(acc[i][j], ah,  BL[j]);
                #pragma unroll
                for (int j = 0; j < NJ; j++) mma_bf16(acc[i][j], al_, BH[j]);
            }
        }
    };

    load_stage(0, 0);
    load_stage(1, 32);

    for (int c = 0; c < NC; c++){
        if (c < NC - 1) asm volatile("cp.async.wait_group 1;" ::: "memory");
        else            asm volatile("cp.async.wait_group 0;" ::: "memory");
        __syncthreads();
        compute(c % 3);
        if (c + 2 < NC) load_stage((c + 2) % 3, (c + 2) * 32);
    }

    #pragma unroll
    for (int i = 0; i < 4; i++){
        int r0 = bm + wm*64 + i*16 + (lane >> 2);
        #pragma unroll
        for (int j = 0; j < NJ; j++){
            int c0 = bn + wn*(NT/4) + j*8 + (lane & 3)*2;
            float b0 = 0.f, b1 = 0.f;
            if (HAS_BIAS){ b0 = bias[c0]; b1 = bias[c0+1]; }
            *(float2*)(C + (size_t)r0 * Ntot + c0)     = make_float2(acc[i][j][0]+b0, acc[i][j][1]+b1);
            *(float2*)(C + (size_t)(r0+8) * Ntot + c0) = make_float2(acc[i][j][2]+b0, acc[i][j][3]+b1);
        }
    }
}

#define GEMM_SMEM_128 (3*(2*TILE_A + 2*128*64))
#define GEMM_SMEM_64  (3*(2*TILE_A + 2*64*64))

// ================= merged weight prep (single launch) =================
__device__ __forceinline__ void tss_body(const float* in, const float* g,
                                         bf16* oh, bf16* ol, int R, int C,
                                         int bx, int by, int tx, int ty){
    __shared__ float tile[32][33];
    int c0 = bx * 32, r0 = by * 32;
    #pragma unroll
    for (int i = 0; i < 32; i += 8){
        int r = r0 + ty + i;
        tile[ty + i][tx] = in[(size_t)r * C + c0 + tx] * g[r];
    }
    __syncthreads();
    #pragma unroll
    for (int i = 0; i < 32; i += 8){
        float v = tile[tx][ty + i];
        bf16 h, l; bsplit(v, h, l);
        size_t o = (size_t)(c0 + ty + i) * R + r0 + tx;
        oh[o] = h; ol[o] = l;
    }
}
__device__ __forceinline__ void fold_body(const float* W, const float* beta,
                                          const float* base, float* out,
                                          int K, int N, int n, int lane){
    float s = 0.f;
    for (int k = lane; k < K; k += 32) s += beta[k] * W[(size_t)k * N + n];
    #pragma unroll
    for (int o = 16; o > 0; o >>= 1) s += __shfl_xor_sync(0xffffffffu, s, o);
    if (lane == 0) out[n] = s + (base ? base[n] : 0.f);
}

__global__ void prep_kernel(const float* __restrict__ Wq, const float* __restrict__ lnqg, const float* __restrict__ lnqb,
                            const float* __restrict__ Wk, const float* __restrict__ lnkg, const float* __restrict__ lnkb, const float* __restrict__ bk,
                            const float* __restrict__ Wv, const float* __restrict__ lnvg, const float* __restrict__ lnvb, const float* __restrict__ bv,
                            const float* __restrict__ Wout,
                            bf16* __restrict__ wqTh, bf16* __restrict__ wqTl,
                            bf16* __restrict__ wkvTh, bf16* __restrict__ wkvTl,
                            bf16* __restrict__ wouth, bf16* __restrict__ woutl,
                            float* __restrict__ biasq, float* __restrict__ biaskv){
    int id = blockIdx.x;
    int tx = threadIdx.x, ty = threadIdx.y;           // (32, 8)
    if (id < 256){
        tss_body(Wq, lnqg, wqTh, wqTl, INNERc, INNERc, id & 15, id >> 4, tx, ty);
    } else if (id < 384){
        int l = id - 256;
        tss_body(Wk, lnkg, wkvTh, wkvTl, DIMc, INNERc, l & 15, l >> 4, tx, ty);
    } else if (id < 512){
        int l = id - 384;
        tss_body(Wv, lnvg, wkvTh + (size_t)INNERc*DIMc, wkvTl + (size_t)INNERc*DIMc,
                 DIMc, INNERc, l & 15, l >> 4, tx, ty);
    } else if (id < 1024){
        int i = (id - 512) * 256 + ty * 32 + tx;
        bf16 h, l; bsplit(Wout[i], h, l);
        wouth[i] = h; woutl[i] = l;
    } else if (id < 1088){
        int n = (id - 1024) * 8 + ty;
        fold_body(Wq, lnqb, nullptr, biasq, INNERc, INNERc, n, tx);
    } else if (id < 1152){
        int n = (id - 1088) * 8 + ty;
        fold_body(Wk, lnkb, bk, biaskv, DIMc, INNERc, n, tx);
    } else {
        int n = (id - 1152) * 8 + ty;
        fold_body(Wv, lnvb, bv, biaskv + INNERc, DIMc, INNERc, n, tx);
    }
}

// ================= merged warp-per-row LayerNorm (lnq + lnkv) =================
__global__ void ln_all_kernel(const float* __restrict__ x, const float* __restrict__ px,
                              bf16* __restrict__ qoh, bf16* __restrict__ qol,
                              bf16* __restrict__ nh, bf16* __restrict__ nl){
    int gw = (blockIdx.x * blockDim.x + threadIdx.x) >> 5;
    int lane = threadIdx.x & 31;
    if (gw < MQ){
        size_t base = (size_t)gw * DIMc + lane * 8;
        float4 a0 = *(const float4*)(x  + base);
        float4 a1 = *(const float4*)(x  + base + 4);
        float4 b0 = *(const float4*)(px + base);
        float4 b1 = *(const float4*)(px + base + 4);
        float va[8] = {a0.x,a0.y,a0.z,a0.w,a1.x,a1.y,a1.z,a1.w};
        float vb[8] = {b0.x,b0.y,b0.z,b0.w,b1.x,b1.y,b1.z,b1.w};
        float s = 0.f, ss = 0.f;
        #pragma unroll
        for (int i = 0; i < 8; i++){ s += va[i] + vb[i]; ss += va[i]*va[i] + vb[i]*vb[i]; }
        #pragma unroll
        for (int o = 16; o > 0; o >>= 1){
            s  += __shfl_xor_sync(0xffffffffu, s, o);
            ss += __shfl_xor_sync(0xffffffffu, ss, o);
        }
        float mean = s * (1.0f/512.0f);
        float var  = ss * (1.0f/512.0f) - mean*mean;
        float rstd = rsqrtf(var + 1e-5f);
        uint32_t ph[4], pl[4];
        #pragma unroll
        for (int i = 0; i < 4; i++){
            bf16 h0,l0,h1,l1;
            bsplit((va[2*i]   - mean)*rstd, h0, l0);
            bsplit((va[2*i+1] - mean)*rstd, h1, l1);
            ph[i] = (uint32_t)__bfloat16_as_ushort(h0) | ((uint32_t)__bfloat16_as_ushort(h1) << 16);
            pl[i] = (uint32_t)__bfloat16_as_ushort(l0) | ((uint32_t)__bfloat16_as_ushort(l1) << 16);
        }
        size_t ob = (size_t)gw * INNERc + lane * 8;
        *(uint4*)(qoh + ob) = make_uint4(ph[0],ph[1],ph[2],ph[3]);
        *(uint4*)(qol + ob) = make_uint4(pl[0],pl[1],pl[2],pl[3]);
        #pragma unroll
        for (int i = 0; i < 4; i++){
            bf16 h0,l0,h1,l1;
            bsplit((vb[2*i]   - mean)*rstd, h0, l0);
            bsplit((vb[2*i+1] - mean)*rstd, h1, l1);
            ph[i] = (uint32_t)__bfloat16_as_ushort(h0) | ((uint32_t)__bfloat16_as_ushort(h1) << 16);
            pl[i] = (uint32_t)__bfloat16_as_ushort(l0) | ((uint32_t)__bfloat16_as_ushort(l1) << 16);
        }
        *(uint4*)(qoh + ob + 256) = make_uint4(ph[0],ph[1],ph[2],ph[3]);
        *(uint4*)(qol + ob + 256) = make_uint4(pl[0],pl[1],pl[2],pl[3]);
    } else {
        int row = gw - MQ;
        const float* src = (row < MQ) ? x : px;
        int r2 = (row < MQ) ? row : row - MQ;
        size_t base = (size_t)r2 * DIMc + lane * 8;
        float4 a0 = *(const float4*)(src + base);
        float4 a1 = *(const float4*)(src + base + 4);
        float v[8] = {a0.x,a0.y,a0.z,a0.w,a1.x,a1.y,a1.z,a1.w};
        float s = 0.f, ss = 0.f;
        #pragma unroll
        for (int i = 0; i < 8; i++){ s += v[i]; ss += v[i]*v[i]; }
        #pragma unroll
        for (int o = 16; o > 0; o >>= 1){
            s  += __shfl_xor_sync(0xffffffffu, s, o);
            ss += __shfl_xor_sync(0xffffffffu, ss, o);
        }
        float mean = s * (1.0f/256.0f);
        float var  = ss * (1.0f/256.0f) - mean*mean;
        float rstd = rsqrtf(var + 1e-5f);
        uint32_t ph[4], pl[4];
        #pragma unroll
        for (int i = 0; i < 4; i++){
            bf16 h0,l0,h1,l1;
            bsplit((v[2*i]   - mean)*rstd, h0, l0);
            bsplit((v[2*i+1] - mean)*rstd, h1, l1);
            ph[i] = (uint32_t)__bfloat16_as_ushort(h0) | ((uint32_t)__bfloat16_as_ushort(h1) << 16);
            pl[i] = (uint32_t)__bfloat16_as_ushort(l0) | ((uint32_t)__bfloat16_as_ushort(l1) << 16);
        }
        size_t ob = (size_t)row * DIMc + lane * 8;
        *(uint4*)(nh + ob) = make_uint4(ph[0],ph[1],ph[2],ph[3]);
        *(uint4*)(nl + ob) = make_uint4(pl[0],pl[1],pl[2],pl[3]);
    }
}

// ============ offsets projection: 8 threads/row, interleaved K, coalesced ====
__global__ void off_kernel(const float* __restrict__ q, const float* __restrict__ Woff,
                           const float* __restrict__ boff, float* __restrict__ off_out) {
    __shared__ float w[16 * INNERc];
    int tid = threadIdx.x;
    for (int i = tid; i < 16 * INNERc / 4; i += 256)
        ((float4*)w)[i] = ((const float4*)Woff)[i];
    __syncthreads();
    int row = blockIdx.x * 32 + (tid >> 3);
    int ks  = tid & 7;
    const float* qr = q + (size_t)row * INNERc;
    float acc[16];
    #pragma unroll
    for (int j = 0; j < 16; j++) acc[j] = 0.f;
    #pragma unroll
    for (int m = 0; m < 16; m++){
        int kb = m * 32 + ks * 4;
        float4 qv = *(const float4*)(qr + kb);
        #pragma unroll
        for (int j = 0; j < 16; j++){
            const float* wj = w + j * INNERc + kb;
            acc[j] += qv.x*wj[0] + qv.y*wj[1] + qv.z*wj[2] + qv.w*wj[3];
        }
    }
    #pragma unroll
    for (int j = 0; j < 16; j++){
        acc[j] += __shfl_xor_sync(0xffffffffu, acc[j], 1);
        acc[j] += __shfl_xor_sync(0xffffffffu, acc[j], 2);
        acc[j] += __shfl_xor_sync(0xffffffffu, acc[j], 4);
    }
    if (ks == 0){
        int b = row >> 12, n = row & 4095;
        #pragma unroll
        for (int j = 0; j < 16; j++)
            off_out[((size_t)(b * 16 + j)) * Nn + n] = acc[j] + boff[j];
    }
}

// ================= attention: 2 heads per warp, hoisted gather loads ==========
__global__ void attn_kernel(const float* __restrict__ q, const float* __restrict__ kv,
                            const float* __restrict__ off_t,
                            bf16* __restrict__ aoh, bf16* __restrict__ aol) {
    int gw = (blockIdx.x * blockDim.x + threadIdx.x) >> 5;   // [0, MQ*4)
    int lane = threadIdx.x & 31;
    if (gw >= MQ * 4) return;
    int bn = gw >> 2;
    int hp = gw & 3;
    int h0 = hp * 2, h1 = hp * 2 + 1;
    int b  = bn / Nn;
    int n  = bn - b * Nn;
    float fn = (float)n;
    const float hi = (float)(2 * Nn - 1);

    // offsets for both heads
    const float* offb = off_t + (size_t)(b * 16) * Nn + n;
    float oA0 = offb[(size_t)(h0 * Pp + 0) * Nn];
    float oA1 = offb[(size_t)(h0 * Pp + 1) * Nn];
    float oB0 = offb[(size_t)(h1 * Pp + 0) * Nn];
    float oB1 = offb[(size_t)(h1 * Pp + 1) * Nn];

    int jA0 = (int)fminf(fmaxf(fn + oA0, 0.f), hi);
    int jA1 = (int)fminf(fmaxf(fn + oA1, 0.f), hi);
    int jB0 = (int)fminf(fmaxf(fn + oB0, 0.f), hi);
    int jB1 = (int)fminf(fmaxf(fn + oB1, 0.f), hi);

    auto rowptr = [&](int j)->const float*{
        int s = (j >= Nn) ? 1 : 0; int np = j - s * Nn;
        return kv + ((size_t)(s * Bsz + b) * Nn + np) * (2*INNERc);
    };
    const float* rA0 = rowptr(jA0) + h0 * DHd;
    const float* rA1 = rowptr(jA1) + h0 * DHd;
    const float* rB0 = rowptr(jB0) + h1 * DHd;
    const float* rB1 = rowptr(jB1) + h1 * DHd;

    const float* qbase = q + (size_t)bn * INNERc;
    // issue all loads up-front
    float qA0 = qbase[h0*DHd + lane],      qA1 = qbase[h0*DHd + lane + 32];
    float qB0 = qbase[h1*DHd + lane],      qB1 = qbase[h1*DHd + lane + 32];
    float kA0a = rA0[lane], kA0b = rA0[lane+32];
    float kA1a = rA1[lane], kA1b = rA1[lane+32];
    float kB0a = rB0[lane], kB0b = rB0[lane+32];
    float kB1a = rB1[lane], kB1b = rB1[lane+32];
    float vA0a = rA0[INNERc+lane], vA0b = rA0[INNERc+lane+32];
    float vA1a = rA1[INNERc+lane], vA1b = rA1[INNERc+lane+32];
    float vB0a = rB0[INNERc+lane], vB0b = rB0[INNERc+lane+32];
    float vB1a = rB1[INNERc+lane], vB1b = rB1[INNERc+lane+32];

    float dA0 = qA0*kA0a + qA1*kA0b;
    float dA1 = qA0*kA1a + qA1*kA1b;
    float dB0 = qB0*kB0a + qB1*kB0b;
    float dB1 = qB0*kB1a + qB1*kB1b;
    #pragma unroll
    for (int o = 16; o > 0; o >>= 1) {
        dA0 += __shfl_xor_sync(0xffffffffu, dA0, o);
        dA1 += __shfl_xor_sync(0xffffffffu, dA1, o);
        dB0 += __shfl_xor_sync(0xffffffffu, dB0, o);
        dB1 += __shfl_xor_sync(0xffffffffu, dB1, o);
    }
    const float scale = 0.125f;
    dA0 *= scale; dA1 *= scale; dB0 *= scale; dB1 *= scale;
    float mA = fmaxf(dA0, dA1), mB = fmaxf(dB0, dB1);
    float eA0 = __expf(dA0 - mA), eA1 = __expf(dA1 - mA);
    float eB0 = __expf(dB0 - mB), eB1 = __expf(dB1 - mB);
    float iA = 1.0f / (eA0 + eA1), iB = 1.0f / (eB0 + eB1);
    float aA0 = eA0 * iA, aA1 = eA1 * iA;
    float aB0 = eB0 * iB, aB1 = eB1 * iB;

    float rAa = aA0*vA0a + aA1*vA1a, rAb = aA0*vA0b + aA1*vA1b;
    float rBa = aB0*vB0a + aB1*vB1a, rBb = aB0*vB0b + aB1*vB1b;

    bf16 hh, ll;
    size_t ob = (size_t)bn * INNERc;
    bsplit(rAa, hh, ll); aoh[ob + h0*DHd + lane]      = hh; aol[ob + h0*DHd + lane]      = ll;
    bsplit(rAb, hh, ll); aoh[ob + h0*DHd + lane + 32] = hh; aol[ob + h0*DHd + lane + 32] = ll;
    bsplit(rBa, hh, ll); aoh[ob + h1*DHd + lane]      = hh; aol[ob + h1*DHd + lane]      = ll;
    bsplit(rBb, hh, ll); aoh[ob + h1*DHd + lane + 32] = hh; aol[ob + h1*DHd + lane + 32] = ll;
}

// ================= launch =================
extern "C" void kernel_launch(void* const* d_in, const int* in_sizes, int n_in,
                              void* d_out, int out_size) {
    const float* x     = (const float*)d_in[0];
    const float* px    = (const float*)d_in[1];
    const float* lnqg  = (const float*)d_in[2];
    const float* lnqb  = (const float*)d_in[3];
    const float* lnkg  = (const float*)d_in[4];
    const float* lnkb  = (const float*)d_in[5];
    const float* lnvg  = (const float*)d_in[6];
    const float* lnvb  = (const float*)d_in[7];
    const float* Wq    = (const float*)d_in[8];
    const float* Wk    = (const float*)d_in[9];
    const float* bk    = (const float*)d_in[10];
    const float* Wv    = (const float*)d_in[11];
    const float* bv    = (const float*)d_in[12];
    const float* Woff  = (const float*)d_in[13];
    const float* boff  = (const float*)d_in[14];
    const float* Wout  = (const float*)d_in[15];
    const float* bout  = (const float*)d_in[16];

    bf16 *qlnh,*qlnl,*nh,*nl,*aoh,*aol;
    bf16 *wqTh,*wqTl,*wkvTh,*wkvTl,*wouth,*woutl;
    float *qb,*kvb,*biasq,*biaskv;
    cudaGetSymbolAddress((void**)&qlnh, g_qlnh);
    cudaGetSymbolAddress((void**)&qlnl, g_qlnl);
    cudaGetSymbolAddress((void**)&qb,   g_q);
    cudaGetSymbolAddress((void**)&nh,   g_nh);
    cudaGetSymbolAddress((void**)&nl,   g_nl);
    cudaGetSymbolAddress((void**)&kvb,  g_kv);
    cudaGetSymbolAddress((void**)&aoh,  g_aoh);
    cudaGetSymbolAddress((void**)&aol,  g_aol);
    cudaGetSymbolAddress((void**)&wqTh, g_wqTh);
    cudaGetSymbolAddress((void**)&wqTl, g_wqTl);
    cudaGetSymbolAddress((void**)&wkvTh, g_wkvTh);
    cudaGetSymbolAddress((void**)&wkvTl, g_wkvTl);
    cudaGetSymbolAddress((void**)&wouth, g_wouth);
    cudaGetSymbolAddress((void**)&woutl, g_woutl);
    cudaGetSymbolAddress((void**)&biasq,  g_biasq);
    cudaGetSymbolAddress((void**)&biaskv, g_biaskv);

    cudaFuncSetAttribute((const void*)bf16x3_gemm<1,128>, cudaFuncAttributeMaxDynamicSharedMemorySize, GEMM_SMEM_128);
    cudaFuncSetAttribute((const void*)bf16x3_gemm<1,64>,  cudaFuncAttributeMaxDynamicSharedMemorySize, GEMM_SMEM_64);

    float* out_main = (float*)d_out;
    float* out_off  = out_main + (size_t)MQ * DIMc;

    // 0: all weight prep
    prep_kernel<<<1216, dim3(32,8)>>>(Wq, lnqg, lnqb, Wk, lnkg, lnkb, bk,
                                      Wv, lnvg, lnvb, bv, Wout,
                                      wqTh, wqTl, wkvTh, wkvTl, wouth, woutl,
                                      biasq, biaskv);
    // 1: merged LN (warp per row)
    ln_all_kernel<<<(MQ + MKV)/8, 256>>>(x, px, qlnh, qlnl, nh, nl);

    // 2: kv = nrm @ [foldedWk | foldedWv] + biaskv
    bf16x3_gemm<1,128><<<dim3(2*INNERc/128, MKV/128), 256, GEMM_SMEM_128>>>(nh, nl, wkvTh, wkvTl, biaskv, kvb, 2*INNERc, DIMc);
    // 3: q = nrm_q @ foldedWq + biasq
    bf16x3_gemm<1,128><<<dim3(INNERc/128, MQ/128),  256, GEMM_SMEM_128>>>(qlnh, qlnl, wqTh, wqTl, biasq, qb, INNERc, INNERc);

    // 4,5: offsets + attention (2 heads/warp)
    off_kernel<<<MQ/32, 256>>>(qb, Woff, boff, out_off);
    attn_kernel<<<(MQ*4)/8, 256>>>(qb, kvb, out_off, aoh, aol);

    // 6: out = ao @ Wout^T + bout
    bf16x3_gemm<1,64><<<dim3(DIMc/64, MQ/128), 256, GEMM_SMEM_64>>>(aoh, aol, wouth, woutl, bout, out_main, DIMc, INNERc);
}

// round 15
// speedup vs baseline: 1.5247x; 1.0164x over previous
#include <cuda_runtime.h>
#include <cuda_bf16.h>
#include <cstdint>
#include <math.h>

#define Bsz 4
#define Nn 4096
#define DIMc 256
#define Hh 8
#define DHd 64
#define Pp 2
#define INNERc 512
#define MQ (Bsz*Nn)      /* 16384 */
#define MKV (2*Bsz*Nn)   /* 32768 */

typedef __nv_bfloat16 bf16;

// ---------------- scratch (device globals) ----------------
__device__ bf16  g_qlnh[MQ * INNERc];
__device__ bf16  g_qlnl[MQ * INNERc];
__device__ float g_q   [MQ * INNERc];
__device__ bf16  g_nh  [MKV * DIMc];
__device__ bf16  g_nl  [MKV * DIMc];
__device__ float g_kv  [MKV * 2 * INNERc];
__device__ bf16  g_aoh [MQ * INNERc];
__device__ bf16  g_aol [MQ * INNERc];
__device__ bf16  g_wqTh[INNERc * INNERc];
__device__ bf16  g_wqTl[INNERc * INNERc];
__device__ bf16  g_wkvTh[2 * INNERc * DIMc];
__device__ bf16  g_wkvTl[2 * INNERc * DIMc];
__device__ bf16  g_wouth[DIMc * INNERc];
__device__ bf16  g_woutl[DIMc * INNERc];
__device__ float g_biasq [INNERc];
__device__ float g_biaskv[2 * INNERc];

// ================= helpers =================
__device__ __forceinline__ uint32_t smem_u32(const void* p){
    uint32_t a;
    asm("{ .reg .u64 t; cvta.to.shared.u64 t, %1; cvt.u32.u64 %0, t; }" : "=r"(a) : "l"(p));
    return a;
}
__device__ __forceinline__ void bsplit(float v, bf16& h, bf16& l){
    h = __float2bfloat16(v);
    l = __float2bfloat16(v - __bfloat162float(h));
}
__device__ __forceinline__ void mma_bf16(float d[4], const uint32_t a[4], const uint32_t b[2]){
    asm volatile("mma.sync.aligned.m16n8k16.row.col.f32.bf16.bf16.f32 "
        "{%0,%1,%2,%3}, {%4,%5,%6,%7}, {%8,%9}, {%0,%1,%2,%3};"
        : "+f"(d[0]),"+f"(d[1]),"+f"(d[2]),"+f"(d[3])
        : "r"(a[0]),"r"(a[1]),"r"(a[2]),"r"(a[3]),"r"(b[0]),"r"(b[1]));
}
__device__ __forceinline__ void ldsm4(uint32_t r[4], uint32_t addr){
    asm volatile("ldmatrix.sync.aligned.m8n8.x4.shared.b16 {%0,%1,%2,%3}, [%4];"
        : "=r"(r[0]),"=r"(r[1]),"=r"(r[2]),"=r"(r[3]) : "r"(addr));
}
__device__ __forceinline__ void cp16(uint32_t dst, const void* src){
    asm volatile("cp.async.cg.shared.global [%0], [%1], 16;" :: "r"(dst), "l"(src));
}
__device__ __forceinline__ uint32_t swz(int r, int s){
    return (uint32_t)(r * 64 + ((s ^ ((r >> 1) & 3)) << 4));
}

// ================= bf16x3 tensor-core GEMM =================
#define TILE_A 8192

template<int HAS_BIAS, int NT>
__global__ void __launch_bounds__(256, 2)
bf16x3_gemm(const bf16* __restrict__ Ah, const bf16* __restrict__ Al,
            const bf16* __restrict__ Bh, const bf16* __restrict__ Bl,
            const float* __restrict__ bias, float* __restrict__ C,
            int Ntot, int K)
{
    cudaGridDependencySynchronize();
    constexpr int NJ  = NT / 32;
    constexpr int NJP = NT / 64;
    constexpr int TILE_BP = NT * 64;
    constexpr int STAGE = 2*TILE_A + 2*TILE_BP;

    extern __shared__ char smem[];
    const uint32_t sb = smem_u32(smem);
    const int tid = threadIdx.x, lane = tid & 31, wid = tid >> 5;
    const int wm = wid >> 2, wn = wid & 3;
    const int bm = blockIdx.y * 128, bn = blockIdx.x * NT;
    const int NC = K >> 5;

    const int lr  = tid >> 2;
    const int lcc = tid & 3;
    const uint32_t w0 = swz(lr, lcc), w1 = swz(lr + 64, lcc);

    const size_t row64 = (size_t)64 * K;
    const bf16* pAh = Ah + (size_t)(bm + lr) * K + lcc * 8;
    const bf16* pAl = Al + (size_t)(bm + lr) * K + lcc * 8;
    const bf16* pBh = Bh + (size_t)(bn + lr) * K + lcc * 8;
    const bf16* pBl = Bl + (size_t)(bn + lr) * K + lcc * 8;

    uint32_t aoff[2][4], boff[2][NJP];
    #pragma unroll
    for (int ks = 0; ks < 2; ks++){
        const int slot = (lane >> 4) + ks * 2;
        #pragma unroll
        for (int i = 0; i < 4; i++)
            aoff[ks][i] = swz(wm*64 + i*16 + (lane & 15), slot);
        #pragma unroll
        for (int jp = 0; jp < NJP; jp++)
            boff[ks][jp] = 2*TILE_A + swz(wn*(NT/4) + jp*16 + (lane & 15), slot);
    }

    auto load_stage = [&](int buf, int kc){
        uint32_t base = sb + buf * STAGE;
        cp16(base + w0,           pAh + kc);
        cp16(base + w1,           pAh + kc + row64);
        cp16(base + TILE_A + w0,  pAl + kc);
        cp16(base + TILE_A + w1,  pAl + kc + row64);
        cp16(base + 2*TILE_A + w0,            pBh + kc);
        cp16(base + 2*TILE_A + TILE_BP + w0,  pBl + kc);
        if (NT == 128){
            cp16(base + 2*TILE_A + w1,           pBh + kc + row64);
            cp16(base + 2*TILE_A + TILE_BP + w1, pBl + kc + row64);
        }
        asm volatile("cp.async.commit_group;" ::: "memory");
    };

    float acc[4][NJ][4] = {};

    auto compute = [&](int buf){
        uint32_t base = sb + buf * STAGE;
        #pragma unroll
        for (int ks = 0; ks < 2; ks++){
            uint32_t BH[NJ][2], BL[NJ][2];
            #pragma unroll
            for (int jp = 0; jp < NJP; jp++){
                uint32_t a = base + boff[ks][jp];
                uint32_t r4[4];
                ldsm4(r4, a);
                BH[jp*2][0]=r4[0]; BH[jp*2+1][0]=r4[1]; BH[jp*2][1]=r4[2]; BH[jp*2+1][1]=r4[3];
                ldsm4(r4, a + TILE_BP);
                BL[jp*2][0]=r4[0]; BL[jp*2+1][0]=r4[1]; BL[jp*2][1]=r4[2]; BL[jp*2+1][1]=r4[3];
            }
            #pragma unroll
            for (int i = 0; i < 4; i++){
                uint32_t a = base + aoff[ks][i];
                uint32_t ah[4], al_[4];
                ldsm4(ah,  a);
                ldsm4(al_, a + TILE_A);
                #pragma unroll
                for (int j = 0; j < NJ; j++) mma_bf16(acc[i][j], ah,  BH[j]);
                #pragma unroll
                for (int j = 0; j < NJ; j++) mma_bf16(acc[i][j], ah,  BL[j]);
                #pragma unroll
                for (int j = 0; j < NJ; j++) mma_bf16(acc[i][j], al_, BH[j]);
            }
        }
    };

    load_stage(0, 0);
    load_stage(1, 32);

    for (int c = 0; c < NC; c++){
        if (c < NC - 1) asm volatile("cp.async.wait_group 1;" ::: "memory");
        else            asm volatile("cp.async.wait_group 0;" ::: "memory");
        __syncthreads();
        compute(c % 3);
        if (c + 2 < NC) load_stage((c + 2) % 3, (c + 2) * 32);
    }

    #pragma unroll
    for (int i = 0; i < 4; i++){
        int r0 = bm + wm*64 + i*16 + (lane >> 2);
        #pragma unroll
        for (int j = 0; j < NJ; j++){
            int c0 = bn + wn*(NT/4) + j*8 + (lane & 3)*2;
            float b0 = 0.f, b1 = 0.f;
            if (HAS_BIAS){ b0 = bias[c0]; b1 = bias[c0+1]; }
            *(float2*)(C + (size_t)r0 * Ntot + c0)     = make_float2(acc[i][j][0]+b0, acc[i][j][1]+b1);
            *(float2*)(C + (size_t)(r0+8) * Ntot + c0) = make_float2(acc[i][j][2]+b0, acc[i][j][3]+b1);
        }
    }
}

#define GEMM_SMEM_128 (3*(2*TILE_A + 2*128*64))
#define GEMM_SMEM_64  (3*(2*TILE_A + 2*64*64))

// ================= merged prep + LN kernel (single launch) =================
// blocks [0, 6144)        : warp-per-row LN (lnq rows then lnkv rows)
// blocks [6144, 6400)     : transpose+scale+split Wq
// blocks [6400, 6528)     : transpose+scale+split Wk
// blocks [6528, 6656)     : transpose+scale+split Wv
// blocks [6656, 7168)     : split Wout
// blocks [7168, 7232)     : fold bias q
// blocks [7232, 7296)     : fold bias k
// blocks [7296, 7360)     : fold bias v
#define LN_BLOCKS ((MQ + MKV)/8)   /* 6144 */

__device__ __forceinline__ void tss_body(const float* in, const float* g,
                                         bf16* oh, bf16* ol, int R, int C,
                                         int bx, int by, int tx, int ty){
    __shared__ float tile[32][33];
    int c0 = bx * 32, r0 = by * 32;
    #pragma unroll
    for (int i = 0; i < 32; i += 8){
        int r = r0 + ty + i;
        tile[ty + i][tx] = in[(size_t)r * C + c0 + tx] * g[r];
    }
    __syncthreads();
    #pragma unroll
    for (int i = 0; i < 32; i += 8){
        float v = tile[tx][ty + i];
        bf16 h, l; bsplit(v, h, l);
        size_t o = (size_t)(c0 + ty + i) * R + r0 + tx;
        oh[o] = h; ol[o] = l;
    }
}
__device__ __forceinline__ void fold_body(const float* W, const float* beta,
                                          const float* base, float* out,
                                          int K, int N, int n, int lane){
    float s = 0.f;
    for (int k = lane; k < K; k += 32) s += beta[k] * W[(size_t)k * N + n];
    #pragma unroll
    for (int o = 16; o > 0; o >>= 1) s += __shfl_xor_sync(0xffffffffu, s, o);
    if (lane == 0) out[n] = s + (base ? base[n] : 0.f);
}

__global__ void prep_ln_kernel(const float* __restrict__ x, const float* __restrict__ px,
                               const float* __restrict__ Wq, const float* __restrict__ lnqg, const float* __restrict__ lnqb,
                               const float* __restrict__ Wk, const float* __restrict__ lnkg, const float* __restrict__ lnkb, const float* __restrict__ bk,
                               const float* __restrict__ Wv, const float* __restrict__ lnvg, const float* __restrict__ lnvb, const float* __restrict__ bv,
                               const float* __restrict__ Wout,
                               bf16* __restrict__ qoh, bf16* __restrict__ qol,
                               bf16* __restrict__ nh, bf16* __restrict__ nl,
                               bf16* __restrict__ wqTh, bf16* __restrict__ wqTl,
                               bf16* __restrict__ wkvTh, bf16* __restrict__ wkvTl,
                               bf16* __restrict__ wouth, bf16* __restrict__ woutl,
                               float* __restrict__ biasq, float* __restrict__ biaskv){
    cudaGridDependencySynchronize();
    int id = blockIdx.x;
    int tid = threadIdx.x;
    if (id < LN_BLOCKS){
        int gw = id * 8 + (tid >> 5);
        int lane = tid & 31;
        if (gw < MQ){
            size_t base = (size_t)gw * DIMc + lane * 8;
            float4 a0 = *(const float4*)(x  + base);
            float4 a1 = *(const float4*)(x  + base + 4);
            float4 b0 = *(const float4*)(px + base);
            float4 b1 = *(const float4*)(px + base + 4);
            float va[8] = {a0.x,a0.y,a0.z,a0.w,a1.x,a1.y,a1.z,a1.w};
            float vb[8] = {b0.x,b0.y,b0.z,b0.w,b1.x,b1.y,b1.z,b1.w};
            float s = 0.f, ss = 0.f;
            #pragma unroll
            for (int i = 0; i < 8; i++){ s += va[i] + vb[i]; ss += va[i]*va[i] + vb[i]*vb[i]; }
            #pragma unroll
            for (int o = 16; o > 0; o >>= 1){
                s  += __shfl_xor_sync(0xffffffffu, s, o);
                ss += __shfl_xor_sync(0xffffffffu, ss, o);
            }
            float mean = s * (1.0f/512.0f);
            float var  = ss * (1.0f/512.0f) - mean*mean;
            float rstd = rsqrtf(var + 1e-5f);
            uint32_t ph[4], pl[4];
            #pragma unroll
            for (int i = 0; i < 4; i++){
                bf16 h0,l0,h1,l1;
                bsplit((va[2*i]   - mean)*rstd, h0, l0);
                bsplit((va[2*i+1] - mean)*rstd, h1, l1);
                ph[i] = (uint32_t)__bfloat16_as_ushort(h0) | ((uint32_t)__bfloat16_as_ushort(h1) << 16);
                pl[i] = (uint32_t)__bfloat16_as_ushort(l0) | ((uint32_t)__bfloat16_as_ushort(l1) << 16);
            }
            size_t ob = (size_t)gw * INNERc + lane * 8;
            *(uint4*)(qoh + ob) = make_uint4(ph[0],ph[1],ph[2],ph[3]);
            *(uint4*)(qol + ob) = make_uint4(pl[0],pl[1],pl[2],pl[3]);
            #pragma unroll
            for (int i = 0; i < 4; i++){
                bf16 h0,l0,h1,l1;
                bsplit((vb[2*i]   - mean)*rstd, h0, l0);
                bsplit((vb[2*i+1] - mean)*rstd, h1, l1);
                ph[i] = (uint32_t)__bfloat16_as_ushort(h0) | ((uint32_t)__bfloat16_as_ushort(h1) << 16);
                pl[i] = (uint32_t)__bfloat16_as_ushort(l0) | ((uint32_t)__bfloat16_as_ushort(l1) << 16);
            }
            *(uint4*)(qoh + ob + 256) = make_uint4(ph[0],ph[1],ph[2],ph[3]);
            *(uint4*)(qol + ob + 256) = make_uint4(pl[0],pl[1],pl[2],pl[3]);
        } else {
            int row = gw - MQ;
            const float* src = (row < MQ) ? x : px;
            int r2 = (row < MQ) ? row : row - MQ;
            size_t base = (size_t)r2 * DIMc + lane * 8;
            float4 a0 = *(const float4*)(src + base);
            float4 a1 = *(const float4*)(src + base + 4);
            float v[8] = {a0.x,a0.y,a0.z,a0.w,a1.x,a1.y,a1.z,a1.w};
            float s = 0.f, ss = 0.f;
            #pragma unroll
            for (int i = 0; i < 8; i++){ s += v[i]; ss += v[i]*v[i]; }
            #pragma unroll
            for (int o = 16; o > 0; o >>= 1){
                s  += __shfl_xor_sync(0xffffffffu, s, o);
                ss += __shfl_xor_sync(0xffffffffu, ss, o);
            }
            float mean = s * (1.0f/256.0f);
            float var  = ss * (1.0f/256.0f) - mean*mean;
            float rstd = rsqrtf(var + 1e-5f);
            uint32_t ph[4], pl[4];
            #pragma unroll
            for (int i = 0; i < 4; i++){
                bf16 h0,l0,h1,l1;
                bsplit((v[2*i]   - mean)*rstd, h0, l0);
                bsplit((v[2*i+1] - mean)*rstd, h1, l1);
                ph[i] = (uint32_t)__bfloat16_as_ushort(h0) | ((uint32_t)__bfloat16_as_ushort(h1) << 16);
                pl[i] = (uint32_t)__bfloat16_as_ushort(l0) | ((uint32_t)__bfloat16_as_ushort(l1) << 16);
            }
            size_t ob = (size_t)row * DIMc + lane * 8;
            *(uint4*)(nh + ob) = make_uint4(ph[0],ph[1],ph[2],ph[3]);
            *(uint4*)(nl + ob) = make_uint4(pl[0],pl[1],pl[2],pl[3]);
        }
        return;
    }
    int pid = id - LN_BLOCKS;
    int tx = tid & 31, ty = tid >> 5;      // (32, 8)
    if (pid < 256){
        tss_body(Wq, lnqg, wqTh, wqTl, INNERc, INNERc, pid & 15, pid >> 4, tx, ty);
    } else if (pid < 384){
        int l = pid - 256;
        tss_body(Wk, lnkg, wkvTh, wkvTl, DIMc, INNERc, l & 15, l >> 4, tx, ty);
    } else if (pid < 512){
        int l = pid - 384;
        tss_body(Wv, lnvg, wkvTh + (size_t)INNERc*DIMc, wkvTl + (size_t)INNERc*DIMc,
                 DIMc, INNERc, l & 15, l >> 4, tx, ty);
    } else if (pid < 1024){
        int i = (pid - 512) * 256 + tid;
        bf16 h, l; bsplit(Wout[i], h, l);
        wouth[i] = h; woutl[i] = l;
    } else if (pid < 1088){
        int n = (pid - 1024) * 8 + ty;
        fold_body(Wq, lnqb, nullptr, biasq, INNERc, INNERc, n, tx);
    } else if (pid < 1152){
        int n = (pid - 1088) * 8 + ty;
        fold_body(Wk, lnkb, bk, biaskv, DIMc, INNERc, n, tx);
    } else {
        int n = (pid - 1152) * 8 + ty;
        fold_body(Wv, lnvb, bv, biaskv + INNERc, DIMc, INNERc, n, tx);
    }
}
#define PREP_LN_BLOCKS (LN_BLOCKS + 1216)

// ============ offsets projection: 8 threads/row, interleaved K, coalesced ====
__global__ void off_kernel(const float* __restrict__ q, const float* __restrict__ Woff,
                           const float* __restrict__ boff, float* __restrict__ off_out) {
    cudaGridDependencySynchronize();
    __shared__ float w[16 * INNERc];
    int tid = threadIdx.x;
    for (int i = tid; i < 16 * INNERc / 4; i += 256)
        ((float4*)w)[i] = ((const float4*)Woff)[i];
    __syncthreads();
    int row = blockIdx.x * 32 + (tid >> 3);
    int ks  = tid & 7;
    const float* qr = q + (size_t)row * INNERc;
    float acc[16];
    #pragma unroll
    for (int j = 0; j < 16; j++) acc[j] = 0.f;
    #pragma unroll
    for (int m = 0; m < 16; m++){
        int kb = m * 32 + ks * 4;
        float4 qv = *(const float4*)(qr + kb);
        #pragma unroll
        for (int j = 0; j < 16; j++){
            const float* wj = w + j * INNERc + kb;
            acc[j] += qv.x*wj[0] + qv.y*wj[1] + qv.z*wj[2] + qv.w*wj[3];
        }
    }
    #pragma unroll
    for (int j = 0; j < 16; j++){
        acc[j] += __shfl_xor_sync(0xffffffffu, acc[j], 1);
        acc[j] += __shfl_xor_sync(0xffffffffu, acc[j], 2);
        acc[j] += __shfl_xor_sync(0xffffffffu, acc[j], 4);
    }
    if (ks == 0){
        int b = row >> 12, n = row & 4095;
        #pragma unroll
        for (int j = 0; j < 16; j++)
            off_out[((size_t)(b * 16 + j)) * Nn + n] = acc[j] + boff[j];
    }
}

// ================= attention: 2 heads per warp, hoisted gather loads ==========
__global__ void attn_kernel(const float* __restrict__ q, const float* __restrict__ kv,
                            const float* __restrict__ off_t,
                            bf16* __restrict__ aoh, bf16* __restrict__ aol) {
    cudaGridDependencySynchronize();
    int gw = (blockIdx.x * blockDim.x + threadIdx.x) >> 5;
    int lane = threadIdx.x & 31;
    if (gw >= MQ * 4) return;
    int bn = gw >> 2;
    int hp = gw & 3;
    int h0 = hp * 2, h1 = hp * 2 + 1;
    int b  = bn / Nn;
    int n  = bn - b * Nn;
    float fn = (float)n;
    const float hi = (float)(2 * Nn - 1);

    const float* offb = off_t + (size_t)(b * 16) * Nn + n;
    float oA0 = offb[(size_t)(h0 * Pp + 0) * Nn];
    float oA1 = offb[(size_t)(h0 * Pp + 1) * Nn];
    float oB0 = offb[(size_t)(h1 * Pp + 0) * Nn];
    float oB1 = offb[(size_t)(h1 * Pp + 1) * Nn];

    int jA0 = (int)fminf(fmaxf(fn + oA0, 0.f), hi);
    int jA1 = (int)fminf(fmaxf(fn + oA1, 0.f), hi);
    int jB0 = (int)fminf(fmaxf(fn + oB0, 0.f), hi);
    int jB1 = (int)fminf(fmaxf(fn + oB1, 0.f), hi);

    auto rowptr = [&](int j)->const float*{
        int s = (j >= Nn) ? 1 : 0; int np = j - s * Nn;
        return kv + ((size_t)(s * Bsz + b) * Nn + np) * (2*INNERc);
    };
    const float* rA0 = rowptr(jA0) + h0 * DHd;
    const float* rA1 = rowptr(jA1) + h0 * DHd;
    const float* rB0 = rowptr(jB0) + h1 * DHd;
    const float* rB1 = rowptr(jB1) + h1 * DHd;

    const float* qbase = q + (size_t)bn * INNERc;
    float qA0 = qbase[h0*DHd + lane],      qA1 = qbase[h0*DHd + lane + 32];
    float qB0 = qbase[h1*DHd + lane],      qB1 = qbase[h1*DHd + lane + 32];
    float kA0a = rA0[lane], kA0b = rA0[lane+32];
    float kA1a = rA1[lane], kA1b = rA1[lane+32];
    float kB0a = rB0[lane], kB0b = rB0[lane+32];
    float kB1a = rB1[lane], kB1b = rB1[lane+32];
    float vA0a = rA0[INNERc+lane], vA0b = rA0[INNERc+lane+32];
    float vA1a = rA1[INNERc+lane], vA1b = rA1[INNERc+lane+32];
    float vB0a = rB0[INNERc+lane], vB0b = rB0[INNERc+lane+32];
    float vB1a = rB1[INNERc+lane], vB1b = rB1[INNERc+lane+32];

    float dA0 = qA0*kA0a + qA1*kA0b;
    float dA1 = qA0*kA1a + qA1*kA1b;
    float dB0 = qB0*kB0a + qB1*kB0b;
    float dB1 = qB0*kB1a + qB1*kB1b;
    #pragma unroll
    for (int o = 16; o > 0; o >>= 1) {
        dA0 += __shfl_xor_sync(0xffffffffu, dA0, o);
        dA1 += __shfl_xor_sync(0xffffffffu, dA1, o);
        dB0 += __shfl_xor_sync(0xffffffffu, dB0, o);
        dB1 += __shfl_xor_sync(0xffffffffu, dB1, o);
    }
    const float scale = 0.125f;
    dA0 *= scale; dA1 *= scale; dB0 *= scale; dB1 *= scale;
    float mA = fmaxf(dA0, dA1), mB = fmaxf(dB0, dB1);
    float eA0 = __expf(dA0 - mA), eA1 = __expf(dA1 - mA);
    float eB0 = __expf(dB0 - mB), eB1 = __expf(dB1 - mB);
    float iA = 1.0f / (eA0 + eA1), iB = 1.0f / (eB0 + eB1);
    float aA0 = eA0 * iA, aA1 = eA1 * iA;
    float aB0 = eB0 * iB, aB1 = eB1 * iB;

    float rAa = aA0*vA0a + aA1*vA1a, rAb = aA0*vA0b + aA1*vA1b;
    float rBa = aB0*vB0a + aB1*vB1a, rBb = aB0*vB0b + aB1*vB1b;

    bf16 hh, ll;
    size_t ob = (size_t)bn * INNERc;
    bsplit(rAa, hh, ll); aoh[ob + h0*DHd + lane]      = hh; aol[ob + h0*DHd + lane]      = ll;
    bsplit(rAb, hh, ll); aoh[ob + h0*DHd + lane + 32] = hh; aol[ob + h0*DHd + lane + 32] = ll;
    bsplit(rBa, hh, ll); aoh[ob + h1*DHd + lane]      = hh; aol[ob + h1*DHd + lane]      = ll;
    bsplit(rBb, hh, ll); aoh[ob + h1*DHd + lane + 32] = hh; aol[ob + h1*DHd + lane + 32] = ll;
}

// ================= launch =================
static void launch_cfg(cudaLaunchConfig_t* cfg, cudaLaunchAttribute* at,
                       dim3 g, dim3 b, size_t sm){
    memset(cfg, 0, sizeof(*cfg));
    at->id = cudaLaunchAttributeProgrammaticStreamSerialization;
    at->val.programmaticStreamSerializationAllowed = 1;
    cfg->gridDim = g; cfg->blockDim = b; cfg->dynamicSmemBytes = sm;
    cfg->stream = 0; cfg->attrs = at; cfg->numAttrs = 1;
}

extern "C" void kernel_launch(void* const* d_in, const int* in_sizes, int n_in,
                              void* d_out, int out_size) {
    const float* x     = (const float*)d_in[0];
    const float* px    = (const float*)d_in[1];
    const float* lnqg  = (const float*)d_in[2];
    const float* lnqb  = (const float*)d_in[3];
    const float* lnkg  = (const float*)d_in[4];
    const float* lnkb  = (const float*)d_in[5];
    const float* lnvg  = (const float*)d_in[6];
    const float* lnvb  = (const float*)d_in[7];
    const float* Wq    = (const float*)d_in[8];
    const float* Wk    = (const float*)d_in[9];
    const float* bk    = (const float*)d_in[10];
    const float* Wv    = (const float*)d_in[11];
    const float* bv    = (const float*)d_in[12];
    const float* Woff  = (const float*)d_in[13];
    const float* boff  = (const float*)d_in[14];
    const float* Wout  = (const float*)d_in[15];
    const float* bout  = (const float*)d_in[16];

    bf16 *qlnh,*qlnl,*nh,*nl,*aoh,*aol;
    bf16 *wqTh,*wqTl,*wkvTh,*wkvTl,*wouth,*woutl;
    float *qb,*kvb,*biasq,*biaskv;
    cudaGetSymbolAddress((void**)&qlnh, g_qlnh);
    cudaGetSymbolAddress((void**)&qlnl, g_qlnl);
    cudaGetSymbolAddress((void**)&qb,   g_q);
    cudaGetSymbolAddress((void**)&nh,   g_nh);
    cudaGetSymbolAddress((void**)&nl,   g_nl);
    cudaGetSymbolAddress((void**)&kvb,  g_kv);
    cudaGetSymbolAddress((void**)&aoh,  g_aoh);
    cudaGetSymbolAddress((void**)&aol,  g_aol);
    cudaGetSymbolAddress((void**)&wqTh, g_wqTh);
    cudaGetSymbolAddress((void**)&wqTl, g_wqTl);
    cudaGetSymbolAddress((void**)&wkvTh, g_wkvTh);
    cudaGetSymbolAddress((void**)&wkvTl, g_wkvTl);
    cudaGetSymbolAddress((void**)&wouth, g_wouth);
    cudaGetSymbolAddress((void**)&woutl, g_woutl);
    cudaGetSymbolAddress((void**)&biasq,  g_biasq);
    cudaGetSymbolAddress((void**)&biaskv, g_biaskv);

    cudaFuncSetAttribute((const void*)bf16x3_gemm<1,128>, cudaFuncAttributeMaxDynamicSharedMemorySize, GEMM_SMEM_128);
    cudaFuncSetAttribute((const void*)bf16x3_gemm<1,64>,  cudaFuncAttributeMaxDynamicSharedMemorySize, GEMM_SMEM_64);

    float* out_main = (float*)d_out;
    float* out_off  = out_main + (size_t)MQ * DIMc;

    cudaLaunchConfig_t cfg; cudaLaunchAttribute at;

    // 0: merged prep + LN
    launch_cfg(&cfg, &at, dim3(PREP_LN_BLOCKS), dim3(256), 0);
    cudaLaunchKernelEx(&cfg, prep_ln_kernel, x, px,
                       Wq, lnqg, lnqb, Wk, lnkg, lnkb, bk, Wv, lnvg, lnvb, bv, Wout,
                       qlnh, qlnl, nh, nl, wqTh, wqTl, wkvTh, wkvTl, wouth, woutl,
                       biasq, biaskv);

    // 1: kv = nrm @ [foldedWk | foldedWv] + biaskv
    launch_cfg(&cfg, &at, dim3(2*INNERc/128, MKV/128), dim3(256), GEMM_SMEM_128);
    cudaLaunchKernelEx(&cfg, bf16x3_gemm<1,128>,
                       (const bf16*)nh, (const bf16*)nl, (const bf16*)wkvTh, (const bf16*)wkvTl,
                       (const float*)biaskv, kvb, (int)(2*INNERc), (int)DIMc);

    // 2: q = nrm_q @ foldedWq + biasq
    launch_cfg(&cfg, &at, dim3(INNERc/128, MQ/128), dim3(256), GEMM_SMEM_128);
    cudaLaunchKernelEx(&cfg, bf16x3_gemm<1,128>,
                       (const bf16*)qlnh, (const bf16*)qlnl, (const bf16*)wqTh, (const bf16*)wqTl,
                       (const float*)biasq, qb, (int)INNERc, (int)INNERc);

    // 3: offsets
    launch_cfg(&cfg, &at, dim3(MQ/32), dim3(256), 0);
    cudaLaunchKernelEx(&cfg, off_kernel, (const float*)qb, Woff, boff, out_off);

    // 4: attention
    launch_cfg(&cfg, &at, dim3((MQ*4)/8), dim3(256), 0);
    cudaLaunchKernelEx(&cfg, attn_kernel, (const float*)qb, (const float*)kvb,
                       (const float*)out_off, aoh, aol);

    // 5: out = ao @ Wout^T + bout
    launch_cfg(&cfg, &at, dim3(DIMc/64, MQ/128), dim3(256), GEMM_SMEM_64);
    cudaLaunchKernelEx(&cfg, bf16x3_gemm<1,64>,
                       (const bf16*)aoh, (const bf16*)aol, (const bf16*)wouth, (const bf16*)woutl,
                       (const float*)bout, out_main, (int)DIMc, (int)INNERc);
}